// round 2
// baseline (speedup 1.0000x reference)
#include <cuda_runtime.h>
#include <math.h>

#define N_NODES 50000
#define N_EDGES 800000
#define HID 256
#define NHEAD 8
#define HDIM 32
#define NLAYER 3
#define ATTN_SCALE 0.17677669529663687f   // 32^-0.5

// ---------------- scratch (static device globals; no allocs allowed) --------
__device__ float g_h[N_NODES * HID];
__device__ float g_q[N_NODES * HID];     // also reused: aggO, head hidden
__device__ float g_k[N_NODES * HID];     // also reused: upd
__device__ float g_v[N_NODES * HID];
__device__ float g_agg[N_NODES * HID];
__device__ float g_attn[N_EDGES * NHEAD];
__device__ float g_asum[N_NODES * NHEAD];
__device__ unsigned int g_maxu;          // orderable-uint encoded global max
__device__ int g_src[N_EDGES];
__device__ int g_dst[N_EDGES];
__device__ int g_is64;                   // 1 if edge_index buffer is int64

// orderable-uint encoding for float atomicMax (0 encodes -inf side)
__device__ __forceinline__ unsigned int f2o(float f) {
    unsigned int u = __float_as_uint(f);
    return (u & 0x80000000u) ? ~u : (u | 0x80000000u);
}
__device__ __forceinline__ float o2f(unsigned int u) {
    return (u & 0x80000000u) ? __uint_as_float(u & 0x7FFFFFFFu)
                             : __uint_as_float(~u);
}

// ---------------- index dtype detection + conversion ------------------------
// If the buffer is int64 (little-endian, values < 2^31), every odd 32-bit word
// of the first entries is 0. If int32, odd words are random node ids.
__global__ void detect_idx(const int* __restrict__ raw) {
    __shared__ int any;
    if (threadIdx.x == 0) any = 0;
    __syncthreads();
    // sample 2048 odd words
    for (int i = threadIdx.x; i < 2048; i += blockDim.x) {
        if (raw[2 * i + 1] != 0) any = 1;
    }
    __syncthreads();
    if (threadIdx.x == 0) g_is64 = any ? 0 : 1;
}

__global__ void convert_idx(const int* __restrict__ raw) {
    int e = blockIdx.x * blockDim.x + threadIdx.x;
    if (e >= N_EDGES) return;
    int is64 = g_is64;
    int s, d;
    if (is64) {
        s = raw[2 * e];                      // low word of int64 src[e]
        d = raw[2 * (N_EDGES + e)];          // low word of int64 dst[e]
    } else {
        s = raw[e];
        d = raw[N_EDGES + e];
    }
    // clamp defensively (garbage would IMA otherwise)
    s = min(max(s, 0), N_NODES - 1);
    d = min(max(d, 0), N_NODES - 1);
    g_src[e] = s;
    g_dst[e] = d;
}

// ---------------- small utility kernels -------------------------------------
__global__ void zero_f(float* p, int n) {
    int i = blockIdx.x * blockDim.x + threadIdx.x;
    if (i < n) p[i] = 0.0f;
}

__global__ void zero_layer_small() {
    int i = blockIdx.x * blockDim.x + threadIdx.x;
    if (i < N_NODES * NHEAD) g_asum[i] = 0.0f;
    if (i == 0) g_maxu = 0u;
}

// ---------------- input projection: h = relu(x @ W_in + b_in) ---------------
__global__ void input_proj(const float* __restrict__ x,
                           const float* __restrict__ W,
                           const float* __restrict__ b) {
    int idx = blockIdx.x * blockDim.x + threadIdx.x;
    if (idx >= N_NODES * HID) return;
    int n = idx >> 8;
    int j = idx & 255;
    float acc = b[j];
#pragma unroll
    for (int f = 0; f < 10; f++) acc += x[n * 10 + f] * W[f * HID + j];
    g_h[idx] = fmaxf(acc, 0.0f);
}

// ---------------- generic tiled GEMM: C = [relu](A(Nr,K) @ B(K,M) + bias) ---
// M must be a multiple of 64. Nr, K arbitrary.
__global__ void gemm_tiled(const float* __restrict__ A,
                           const float* __restrict__ B,
                           const float* __restrict__ bias,
                           float* __restrict__ C,
                           int Nr, int K, int M, int relu) {
    __shared__ float As[16][64];
    __shared__ float Bs[16][64];
    int tid = threadIdx.x;        // 256 threads
    int tx = tid & 15;
    int ty = tid >> 4;
    int row0 = blockIdx.y * 64;
    int col0 = blockIdx.x * 64;
    float acc[4][4] = {};

    for (int k0 = 0; k0 < K; k0 += 16) {
#pragma unroll
        for (int i = 0; i < 4; i++) {
            int lin = tid + i * 256;
            int m = lin >> 4, kk = lin & 15;
            int r = row0 + m, kg = k0 + kk;
            As[kk][m] = (r < Nr && kg < K) ? A[r * K + kg] : 0.0f;
        }
#pragma unroll
        for (int i = 0; i < 4; i++) {
            int lin = tid + i * 256;
            int kk = lin >> 6, n = lin & 63;
            int kg = k0 + kk;
            Bs[kk][n] = (kg < K) ? B[kg * M + col0 + n] : 0.0f;
        }
        __syncthreads();
#pragma unroll
        for (int kk = 0; kk < 16; kk++) {
            float4 a = *reinterpret_cast<const float4*>(&As[kk][ty * 4]);
            float4 b = *reinterpret_cast<const float4*>(&Bs[kk][tx * 4]);
            float av[4] = {a.x, a.y, a.z, a.w};
            float bv[4] = {b.x, b.y, b.z, b.w};
#pragma unroll
            for (int i = 0; i < 4; i++)
#pragma unroll
                for (int j = 0; j < 4; j++) acc[i][j] += av[i] * bv[j];
        }
        __syncthreads();
    }

#pragma unroll
    for (int i = 0; i < 4; i++) {
        int r = row0 + ty * 4 + i;
        if (r >= Nr) continue;
#pragma unroll
        for (int j = 0; j < 4; j++) {
            int c = col0 + tx * 4 + j;
            float v = acc[i][j];
            if (bias) v += bias[c];
            if (relu) v = fmaxf(v, 0.0f);
            C[r * M + c] = v;
        }
    }
}

// -------- concat GEMM: C = relu(concat([A1,A2], axis=1)(Nr,512) @ B + bias) -
__global__ void gemm_concat(const float* __restrict__ A1,
                            const float* __restrict__ A2,
                            const float* __restrict__ B,
                            const float* __restrict__ bias,
                            float* __restrict__ C,
                            int Nr, int M) {
    __shared__ float As[16][64];
    __shared__ float Bs[16][64];
    int tid = threadIdx.x;
    int tx = tid & 15;
    int ty = tid >> 4;
    int row0 = blockIdx.y * 64;
    int col0 = blockIdx.x * 64;
    float acc[4][4] = {};

    for (int k0 = 0; k0 < 512; k0 += 16) {
        const float* Asrc = (k0 < 256) ? A1 : A2;
        int kb = k0 & 255;
#pragma unroll
        for (int i = 0; i < 4; i++) {
            int lin = tid + i * 256;
            int m = lin >> 4, kk = lin & 15;
            int r = row0 + m;
            As[kk][m] = (r < Nr) ? Asrc[r * 256 + kb + kk] : 0.0f;
        }
#pragma unroll
        for (int i = 0; i < 4; i++) {
            int lin = tid + i * 256;
            int kk = lin >> 6, n = lin & 63;
            Bs[kk][n] = B[(k0 + kk) * M + col0 + n];
        }
        __syncthreads();
#pragma unroll
        for (int kk = 0; kk < 16; kk++) {
            float4 a = *reinterpret_cast<const float4*>(&As[kk][ty * 4]);
            float4 b = *reinterpret_cast<const float4*>(&Bs[kk][tx * 4]);
            float av[4] = {a.x, a.y, a.z, a.w};
            float bv[4] = {b.x, b.y, b.z, b.w};
#pragma unroll
            for (int i = 0; i < 4; i++)
#pragma unroll
                for (int j = 0; j < 4; j++) acc[i][j] += av[i] * bv[j];
        }
        __syncthreads();
    }

#pragma unroll
    for (int i = 0; i < 4; i++) {
        int r = row0 + ty * 4 + i;
        if (r >= Nr) continue;
#pragma unroll
        for (int j = 0; j < 4; j++) {
            int c = col0 + tx * 4 + j;
            float v = fmaxf(acc[i][j] + bias[c], 0.0f);
            C[r * M + c] = v;
        }
    }
}

// ---------------- edge attention: attn = leaky(scale*<Q[d],K[s]> + eb) ------
__global__ void attn_kernel(const float* __restrict__ edge_attr,
                            const float* __restrict__ We_l) {
    int idx = blockIdx.x * blockDim.x + threadIdx.x;
    float a = -3.4e38f;
    if (idx < N_EDGES * NHEAD) {
        int e = idx >> 3;
        int nh = idx & 7;
        int s = g_src[e];
        int d = g_dst[e];
        const float4* q4 =
            reinterpret_cast<const float4*>(g_q + d * HID + nh * HDIM);
        const float4* k4 =
            reinterpret_cast<const float4*>(g_k + s * HID + nh * HDIM);
        float acc = 0.0f;
#pragma unroll
        for (int i = 0; i < 8; i++) {
            float4 qa = q4[i];
            float4 ka = k4[i];
            acc += qa.x * ka.x + qa.y * ka.y + qa.z * ka.z + qa.w * ka.w;
        }
        float eb = edge_attr[e * 3 + 0] * We_l[nh] +
                   edge_attr[e * 3 + 1] * We_l[8 + nh] +
                   edge_attr[e * 3 + 2] * We_l[16 + nh];
        a = acc * ATTN_SCALE + eb;
        a = (a > 0.0f) ? a : 0.2f * a;       // leaky_relu, slope 0.2
        g_attn[idx] = a;
    }
    // block max -> atomicMax (orderable uint)
    __shared__ float smax[8];
    float w = a;
#pragma unroll
    for (int o = 16; o > 0; o >>= 1)
        w = fmaxf(w, __shfl_down_sync(0xffffffffu, w, o));
    int warp = threadIdx.x >> 5, lane = threadIdx.x & 31;
    if (lane == 0) smax[warp] = w;
    __syncthreads();
    if (warp == 0) {
        w = (lane < 8) ? smax[lane] : -3.4e38f;
#pragma unroll
        for (int o = 4; o > 0; o >>= 1)
            w = fmaxf(w, __shfl_down_sync(0xffffffffu, w, o));
        if (lane == 0) atomicMax(&g_maxu, f2o(w));
    }
}

// ---------------- exp(attn - max) and per-(dst,head) segment sum ------------
__global__ void exp_sum_kernel() {
    int idx = blockIdx.x * blockDim.x + threadIdx.x;
    if (idx >= N_EDGES * NHEAD) return;
    float m = o2f(g_maxu);
    float v = expf(g_attn[idx] - m);
    g_attn[idx] = v;
    int e = idx >> 3;
    int nh = idx & 7;
    int d = g_dst[e];
    atomicAdd(&g_asum[d * NHEAD + nh], v);
}

// ---------------- weighted V aggregation (scatter with REDG) ----------------
// one block (256 threads) per edge: c = threadIdx.x in [0,256)
__global__ void agg_kernel() {
    int e = blockIdx.x;
    int c = threadIdx.x;
    int s = g_src[e];
    int d = g_dst[e];
    int nh = c >> 5;
    float coeff = g_attn[e * NHEAD + nh] /
                  fmaxf(g_asum[d * NHEAD + nh], 1e-12f);
    atomicAdd(&g_agg[d * HID + c], g_v[s * HID + c] * coeff);
}

// ---------------- residual + LayerNorm: h = LN(h + upd)*gamma + beta --------
__global__ void ln_kernel(const float* __restrict__ upd,
                          const float* __restrict__ gamma_l,
                          const float* __restrict__ beta_l) {
    int n = blockIdx.x;
    int t = threadIdx.x;   // 256
    float x = g_h[n * HID + t] + upd[n * HID + t];
    __shared__ float s1[8], s2[8];
    float a = x, b = x * x;
#pragma unroll
    for (int o = 16; o > 0; o >>= 1) {
        a += __shfl_down_sync(0xffffffffu, a, o);
        b += __shfl_down_sync(0xffffffffu, b, o);
    }
    int warp = t >> 5, lane = t & 31;
    if (lane == 0) { s1[warp] = a; s2[warp] = b; }
    __syncthreads();
    if (warp == 0) {
        a = (lane < 8) ? s1[lane] : 0.0f;
        b = (lane < 8) ? s2[lane] : 0.0f;
#pragma unroll
        for (int o = 4; o > 0; o >>= 1) {
            a += __shfl_down_sync(0xffffffffu, a, o);
            b += __shfl_down_sync(0xffffffffu, b, o);
        }
        if (lane == 0) { s1[0] = a; s2[0] = b; }
    }
    __syncthreads();
    float mu = s1[0] * (1.0f / HID);
    float var = s2[0] * (1.0f / HID) - mu * mu;
    g_h[n * HID + t] = (x - mu) * rsqrtf(var + 1e-5f) * gamma_l[t] + beta_l[t];
}

// ---------------- output head 2: out = hidden(N,128) @ W2(128,1) + b2 -------
__global__ void head2_kernel(const float* __restrict__ hidden,
                             const float* __restrict__ W2,
                             const float* __restrict__ b2,
                             float* __restrict__ out) {
    int gw = (blockIdx.x * blockDim.x + threadIdx.x) >> 5;
    int lane = threadIdx.x & 31;
    if (gw >= N_NODES) return;
    float acc = 0.0f;
#pragma unroll
    for (int i = 0; i < 4; i++) {
        int c = lane + i * 32;
        acc += hidden[gw * 128 + c] * W2[c];
    }
#pragma unroll
    for (int o = 16; o > 0; o >>= 1)
        acc += __shfl_down_sync(0xffffffffu, acc, o);
    if (lane == 0) out[gw] = acc + b2[0];
}

// ---------------- launch ----------------------------------------------------
extern "C" void kernel_launch(void* const* d_in, const int* in_sizes, int n_in,
                              void* d_out, int out_size) {
    const float* x         = (const float*)d_in[0];
    const float* edge_attr = (const float*)d_in[1];
    const float* W_in      = (const float*)d_in[2];
    const float* b_in      = (const float*)d_in[3];
    const float* Wq        = (const float*)d_in[4];
    const float* Wk        = (const float*)d_in[5];
    const float* Wv        = (const float*)d_in[6];
    const float* We        = (const float*)d_in[7];
    const float* Wo        = (const float*)d_in[8];
    const float* bo        = (const float*)d_in[9];
    const float* Wm        = (const float*)d_in[10];
    const float* bm        = (const float*)d_in[11];
    const float* gamma     = (const float*)d_in[12];
    const float* beta      = (const float*)d_in[13];
    const float* Wh1       = (const float*)d_in[14];
    const float* bh1       = (const float*)d_in[15];
    const float* Wh2       = (const float*)d_in[16];
    const float* bh2       = (const float*)d_in[17];
    const int*   ei_raw    = (const int*)d_in[18];

    float *ph, *pq, *pk, *pv, *pagg;
    cudaGetSymbolAddress((void**)&ph,   g_h);
    cudaGetSymbolAddress((void**)&pq,   g_q);
    cudaGetSymbolAddress((void**)&pk,   g_k);
    cudaGetSymbolAddress((void**)&pv,   g_v);
    cudaGetSymbolAddress((void**)&pagg, g_agg);

    const int NH_ELEMS = N_NODES * HID;

    // decode edge indices (handles int32 or int64 storage)
    detect_idx<<<1, 256>>>(ei_raw);
    convert_idx<<<(N_EDGES + 255) / 256, 256>>>(ei_raw);

    input_proj<<<(NH_ELEMS + 255) / 256, 256>>>(x, W_in, b_in);

    dim3 gridH(HID / 64, (N_NODES + 63) / 64);

    for (int l = 0; l < NLAYER; l++) {
        const float* Wq_l = Wq + l * HID * HID;
        const float* Wk_l = Wk + l * HID * HID;
        const float* Wv_l = Wv + l * HID * HID;
        const float* We_l = We + l * 3 * NHEAD;
        const float* Wo_l = Wo + l * HID * HID;
        const float* bo_l = bo + l * HID;
        const float* Wm_l = Wm + l * 2 * HID * HID;
        const float* bm_l = bm + l * HID;
        const float* ga_l = gamma + l * HID;
        const float* be_l = beta + l * HID;

        gemm_tiled<<<gridH, 256>>>(ph, Wq_l, nullptr, pq, N_NODES, HID, HID, 0);
        gemm_tiled<<<gridH, 256>>>(ph, Wk_l, nullptr, pk, N_NODES, HID, HID, 0);
        gemm_tiled<<<gridH, 256>>>(ph, Wv_l, nullptr, pv, N_NODES, HID, HID, 0);

        zero_layer_small<<<(N_NODES * NHEAD + 255) / 256, 256>>>();
        zero_f<<<(NH_ELEMS + 255) / 256, 256>>>(pagg, NH_ELEMS);

        attn_kernel<<<(N_EDGES * NHEAD + 255) / 256, 256>>>(edge_attr, We_l);
        exp_sum_kernel<<<(N_EDGES * NHEAD + 255) / 256, 256>>>();
        agg_kernel<<<N_EDGES, 256>>>();

        // aggO = agg @ Wo + bo   (reuse g_q)
        gemm_tiled<<<gridH, 256>>>(pagg, Wo_l, bo_l, pq, N_NODES, HID, HID, 0);
        // upd = relu(concat([h, aggO]) @ Wm + bm)   (reuse g_k)
        gemm_concat<<<gridH, 256>>>(ph, pq, Wm_l, bm_l, pk, N_NODES, HID);
        // h = LN(h + upd) * gamma + beta
        ln_kernel<<<N_NODES, 256>>>(pk, ga_l, be_l);
    }

    // head: hidden = relu(h @ Wh1 + bh1)  (reuse g_q), out = hidden @ Wh2 + bh2
    dim3 gridHead(128 / 64, (N_NODES + 63) / 64);
    gemm_tiled<<<gridHead, 256>>>(ph, Wh1, bh1, pq, N_NODES, HID, 128, 1);
    head2_kernel<<<(N_NODES * 32 + 255) / 256, 256>>>(pq, Wh2, bh2,
                                                      (float*)d_out);
}

// round 3
// speedup vs baseline: 2.4481x; 2.4481x over previous
#include <cuda_runtime.h>
#include <math.h>

#define N_NODES 50000
#define N_EDGES 800000
#define HID 256
#define NHEAD 8
#define HDIM 32
#define NLAYER 3
#define ATTN_SCALE 0.17677669529663687f   // 32^-0.5

// ---------------- scratch (static device globals; no allocs allowed) --------
__device__ float g_h[N_NODES * HID];
__device__ float g_q[N_NODES * HID];     // also reused: aggO, head hidden
__device__ float g_k[N_NODES * HID];     // also reused: upd
__device__ float g_v[N_NODES * HID];
__device__ float g_agg[N_NODES * HID];
__device__ float g_attn[N_EDGES * NHEAD];
__device__ unsigned int g_maxu;          // orderable-uint encoded global max
__device__ int g_src[N_EDGES];
__device__ int g_dst[N_EDGES];
__device__ int g_perm[N_EDGES];          // edges sorted by dst (CSR)
__device__ int g_rowstart[N_NODES + 1];
__device__ int g_cnt[N_NODES];
__device__ int g_cursor[N_NODES];
__device__ int g_is64;

// orderable-uint encoding for float atomicMax
__device__ __forceinline__ unsigned int f2o(float f) {
    unsigned int u = __float_as_uint(f);
    return (u & 0x80000000u) ? ~u : (u | 0x80000000u);
}
__device__ __forceinline__ float o2f(unsigned int u) {
    return (u & 0x80000000u) ? __uint_as_float(u & 0x7FFFFFFFu)
                             : __uint_as_float(~u);
}

// ---------------- index dtype detection + conversion ------------------------
__global__ void detect_idx(const int* __restrict__ raw) {
    __shared__ int any;
    if (threadIdx.x == 0) any = 0;
    __syncthreads();
    for (int i = threadIdx.x; i < 2048; i += blockDim.x)
        if (raw[2 * i + 1] != 0) any = 1;
    __syncthreads();
    if (threadIdx.x == 0) g_is64 = any ? 0 : 1;
}

__global__ void convert_idx(const int* __restrict__ raw) {
    int e = blockIdx.x * blockDim.x + threadIdx.x;
    if (e >= N_EDGES) return;
    int s, d;
    if (g_is64) {
        s = raw[2 * e];
        d = raw[2 * (N_EDGES + e)];
    } else {
        s = raw[e];
        d = raw[N_EDGES + e];
    }
    s = min(max(s, 0), N_NODES - 1);
    d = min(max(d, 0), N_NODES - 1);
    g_src[e] = s;
    g_dst[e] = d;
}

// ---------------- CSR build --------------------------------------------------
__global__ void zero_cnt() {
    int i = blockIdx.x * blockDim.x + threadIdx.x;
    if (i < N_NODES) g_cnt[i] = 0;
    if (i == 0) g_maxu = 0u;
}

__global__ void count_deg() {
    int e = blockIdx.x * blockDim.x + threadIdx.x;
    if (e >= N_EDGES) return;
    atomicAdd(&g_cnt[g_dst[e]], 1);
}

__global__ void scan_rowstart() {     // 1 block, 1024 threads
    __shared__ int sm[1024];
    int t = threadIdx.x;
    int run = 0;
    for (int base = 0; base < N_NODES; base += 1024) {
        int idx = base + t;
        int v = (idx < N_NODES) ? g_cnt[idx] : 0;
        sm[t] = v;
        __syncthreads();
        for (int off = 1; off < 1024; off <<= 1) {
            int x = (t >= off) ? sm[t - off] : 0;
            __syncthreads();
            sm[t] += x;
            __syncthreads();
        }
        if (idx < N_NODES) g_rowstart[idx] = run + sm[t] - v;
        run += sm[1023];
        __syncthreads();
    }
    if (t == 0) g_rowstart[N_NODES] = run;
}

__global__ void copy_cursor() {
    int i = blockIdx.x * blockDim.x + threadIdx.x;
    if (i < N_NODES) g_cursor[i] = g_rowstart[i];
}

__global__ void scatter_perm() {
    int e = blockIdx.x * blockDim.x + threadIdx.x;
    if (e >= N_EDGES) return;
    int pos = atomicAdd(&g_cursor[g_dst[e]], 1);
    g_perm[pos] = e;
}

__global__ void zero_maxu() { g_maxu = 0u; }

// ---------------- input projection: h = relu(x @ W_in + b_in) ---------------
__global__ void input_proj(const float* __restrict__ x,
                           const float* __restrict__ W,
                           const float* __restrict__ b) {
    int idx = blockIdx.x * blockDim.x + threadIdx.x;
    if (idx >= N_NODES * HID) return;
    int n = idx >> 8;
    int j = idx & 255;
    float acc = b[j];
#pragma unroll
    for (int f = 0; f < 10; f++) acc += x[n * 10 + f] * W[f * HID + j];
    g_h[idx] = fmaxf(acc, 0.0f);
}

// ---------------- 128x128x8 tiled GEMM, 8x8 per-thread register tile --------
// C(Nr,M) = [relu](A(Nr,K) @ B(K,M) + bias). K % 8 == 0, M % 128 == 0,
// K % 4 == 0 for float4 A loads. 256 threads.
__global__ __launch_bounds__(256, 2)
void gemm128(const float* __restrict__ A,
             const float* __restrict__ B,
             const float* __restrict__ bias,
             float* __restrict__ C,
             int Nr, int K, int M, int relu) {
    __shared__ __align__(16) float As[8][132];
    __shared__ __align__(16) float Bs[8][128];
    int tid = threadIdx.x;
    int tx = tid & 15;          // 16 -> col groups of 8
    int ty = tid >> 4;          // 16 -> row groups of 8
    int row0 = blockIdx.y * 128;
    int col0 = blockIdx.x * 128;

    // A-load mapping: thread -> row m = tid>>1, k-offset kk0 = (tid&1)*4
    int a_m = tid >> 1;
    int a_k0 = (tid & 1) * 4;
    // B-load mapping: kk = tid>>5, n0 = (tid&31)*4
    int b_kk = tid >> 5;
    int b_n0 = (tid & 31) * 4;

    float acc[8][8] = {};

    for (int k0 = 0; k0 < K; k0 += 8) {
        // load A tile (128 x 8)
        {
            int r = row0 + a_m;
            float4 av = make_float4(0.f, 0.f, 0.f, 0.f);
            if (r < Nr)
                av = *reinterpret_cast<const float4*>(&A[r * K + k0 + a_k0]);
            As[a_k0 + 0][a_m] = av.x;
            As[a_k0 + 1][a_m] = av.y;
            As[a_k0 + 2][a_m] = av.z;
            As[a_k0 + 3][a_m] = av.w;
        }
        // load B tile (8 x 128)
        {
            float4 bv = *reinterpret_cast<const float4*>(
                &B[(k0 + b_kk) * M + col0 + b_n0]);
            *reinterpret_cast<float4*>(&Bs[b_kk][b_n0]) = bv;
        }
        __syncthreads();
#pragma unroll
        for (int kk = 0; kk < 8; kk++) {
            float4 a0 = *reinterpret_cast<const float4*>(&As[kk][ty * 8]);
            float4 a1 = *reinterpret_cast<const float4*>(&As[kk][ty * 8 + 4]);
            float4 b0 = *reinterpret_cast<const float4*>(&Bs[kk][tx * 8]);
            float4 b1 = *reinterpret_cast<const float4*>(&Bs[kk][tx * 8 + 4]);
            float av[8] = {a0.x, a0.y, a0.z, a0.w, a1.x, a1.y, a1.z, a1.w};
            float bv[8] = {b0.x, b0.y, b0.z, b0.w, b1.x, b1.y, b1.z, b1.w};
#pragma unroll
            for (int i = 0; i < 8; i++)
#pragma unroll
                for (int j = 0; j < 8; j++) acc[i][j] += av[i] * bv[j];
        }
        __syncthreads();
    }

    int cbase = col0 + tx * 8;
    float bb[8];
#pragma unroll
    for (int j = 0; j < 8; j++) bb[j] = bias ? bias[cbase + j] : 0.0f;
#pragma unroll
    for (int i = 0; i < 8; i++) {
        int r = row0 + ty * 8 + i;
        if (r >= Nr) continue;
        float o[8];
#pragma unroll
        for (int j = 0; j < 8; j++) {
            float v = acc[i][j] + bb[j];
            o[j] = relu ? fmaxf(v, 0.0f) : v;
        }
        *reinterpret_cast<float4*>(&C[r * M + cbase]) =
            make_float4(o[0], o[1], o[2], o[3]);
        *reinterpret_cast<float4*>(&C[r * M + cbase + 4]) =
            make_float4(o[4], o[5], o[6], o[7]);
    }
}

// -------- concat GEMM: C = relu(concat([A1,A2],1)(Nr,512) @ B(512,M) + bias)
__global__ __launch_bounds__(256, 2)
void gemm128_concat(const float* __restrict__ A1,
                    const float* __restrict__ A2,
                    const float* __restrict__ B,
                    const float* __restrict__ bias,
                    float* __restrict__ C,
                    int Nr, int M) {
    __shared__ __align__(16) float As[8][132];
    __shared__ __align__(16) float Bs[8][128];
    int tid = threadIdx.x;
    int tx = tid & 15;
    int ty = tid >> 4;
    int row0 = blockIdx.y * 128;
    int col0 = blockIdx.x * 128;

    int a_m = tid >> 1;
    int a_k0 = (tid & 1) * 4;
    int b_kk = tid >> 5;
    int b_n0 = (tid & 31) * 4;

    float acc[8][8] = {};

    for (int k0 = 0; k0 < 512; k0 += 8) {
        const float* Asrc = (k0 < 256) ? A1 : A2;
        int kb = k0 & 255;
        {
            int r = row0 + a_m;
            float4 av = make_float4(0.f, 0.f, 0.f, 0.f);
            if (r < Nr)
                av = *reinterpret_cast<const float4*>(
                    &Asrc[r * 256 + kb + a_k0]);
            As[a_k0 + 0][a_m] = av.x;
            As[a_k0 + 1][a_m] = av.y;
            As[a_k0 + 2][a_m] = av.z;
            As[a_k0 + 3][a_m] = av.w;
        }
        {
            float4 bv = *reinterpret_cast<const float4*>(
                &B[(k0 + b_kk) * M + col0 + b_n0]);
            *reinterpret_cast<float4*>(&Bs[b_kk][b_n0]) = bv;
        }
        __syncthreads();
#pragma unroll
        for (int kk = 0; kk < 8; kk++) {
            float4 a0 = *reinterpret_cast<const float4*>(&As[kk][ty * 8]);
            float4 a1 = *reinterpret_cast<const float4*>(&As[kk][ty * 8 + 4]);
            float4 b0 = *reinterpret_cast<const float4*>(&Bs[kk][tx * 8]);
            float4 b1 = *reinterpret_cast<const float4*>(&Bs[kk][tx * 8 + 4]);
            float av[8] = {a0.x, a0.y, a0.z, a0.w, a1.x, a1.y, a1.z, a1.w};
            float bv[8] = {b0.x, b0.y, b0.z, b0.w, b1.x, b1.y, b1.z, b1.w};
#pragma unroll
            for (int i = 0; i < 8; i++)
#pragma unroll
                for (int j = 0; j < 8; j++) acc[i][j] += av[i] * bv[j];
        }
        __syncthreads();
    }

    int cbase = col0 + tx * 8;
    float bb[8];
#pragma unroll
    for (int j = 0; j < 8; j++) bb[j] = bias[cbase + j];
#pragma unroll
    for (int i = 0; i < 8; i++) {
        int r = row0 + ty * 8 + i;
        if (r >= Nr) continue;
        float o[8];
#pragma unroll
        for (int j = 0; j < 8; j++) o[j] = fmaxf(acc[i][j] + bb[j], 0.0f);
        *reinterpret_cast<float4*>(&C[r * M + cbase]) =
            make_float4(o[0], o[1], o[2], o[3]);
        *reinterpret_cast<float4*>(&C[r * M + cbase + 4]) =
            make_float4(o[4], o[5], o[6], o[7]);
    }
}

// ---------------- edge attention: attn = leaky(scale*<Q[d],K[s]> + eb) ------
__global__ void attn_kernel(const float* __restrict__ edge_attr,
                            const float* __restrict__ We_l) {
    int idx = blockIdx.x * blockDim.x + threadIdx.x;
    float a = -3.4e38f;
    if (idx < N_EDGES * NHEAD) {
        int e = idx >> 3;
        int nh = idx & 7;
        int s = g_src[e];
        int d = g_dst[e];
        const float4* q4 =
            reinterpret_cast<const float4*>(g_q + d * HID + nh * HDIM);
        const float4* k4 =
            reinterpret_cast<const float4*>(g_k + s * HID + nh * HDIM);
        float acc = 0.0f;
#pragma unroll
        for (int i = 0; i < 8; i++) {
            float4 qa = q4[i];
            float4 ka = k4[i];
            acc += qa.x * ka.x + qa.y * ka.y + qa.z * ka.z + qa.w * ka.w;
        }
        float eb = edge_attr[e * 3 + 0] * We_l[nh] +
                   edge_attr[e * 3 + 1] * We_l[8 + nh] +
                   edge_attr[e * 3 + 2] * We_l[16 + nh];
        a = acc * ATTN_SCALE + eb;
        a = (a > 0.0f) ? a : 0.2f * a;       // leaky_relu
        g_attn[idx] = a;
    }
    __shared__ float smax[8];
    float w = a;
#pragma unroll
    for (int o = 16; o > 0; o >>= 1)
        w = fmaxf(w, __shfl_down_sync(0xffffffffu, w, o));
    int warp = threadIdx.x >> 5, lane = threadIdx.x & 31;
    if (lane == 0) smax[warp] = w;
    __syncthreads();
    if (warp == 0) {
        w = (lane < 8) ? smax[lane] : -3.4e38f;
#pragma unroll
        for (int o = 4; o > 0; o >>= 1)
            w = fmaxf(w, __shfl_down_sync(0xffffffffu, w, o));
        if (lane == 0) atomicMax(&g_maxu, f2o(w));
    }
}

// ---------------- per-node softmax (CSR): one warp per node -----------------
// Replaces g_attn[e][h] with normalized coefficient exp(a-m)/sum.
__global__ void node_softmax() {
    int warp = threadIdx.x >> 5;
    int lane = threadIdx.x & 31;
    int n = blockIdx.x * 8 + warp;
    if (n >= N_NODES) return;
    int row = g_rowstart[n];
    int deg = g_rowstart[n + 1] - row;
    if (deg == 0) return;
    float m = o2f(g_maxu);
#pragma unroll
    for (int h = 0; h < NHEAD; h++) {
        float sum = 0.0f;
        for (int j = lane; j < deg; j += 32) {
            int e = g_perm[row + j];
            sum += __expf(g_attn[e * NHEAD + h] - m);
        }
#pragma unroll
        for (int o = 16; o > 0; o >>= 1)
            sum += __shfl_xor_sync(0xffffffffu, sum, o);
        float inv = 1.0f / fmaxf(sum, 1e-12f);
        for (int j = lane; j < deg; j += 32) {
            int e = g_perm[row + j];
            float v = __expf(g_attn[e * NHEAD + h] - m);
            g_attn[e * NHEAD + h] = v * inv;
        }
    }
}

// ---------------- weighted V aggregation (CSR gather, no atomics) -----------
// one block (256 threads = channels) per node
__global__ void agg_gather() {
    __shared__ int s_e[256];
    __shared__ int s_s[256];
    int n = blockIdx.x;
    int c = threadIdx.x;
    int nh = c >> 5;
    int row = g_rowstart[n];
    int deg = g_rowstart[n + 1] - row;
    float acc = 0.0f;
    for (int chunk = 0; chunk < deg; chunk += 256) {
        int j = chunk + c;
        if (j < deg) {
            int e = g_perm[row + j];
            s_e[c] = e;
            s_s[c] = g_src[e];
        }
        __syncthreads();
        int cnt = min(256, deg - chunk);
        for (int jj = 0; jj < cnt; jj++) {
            int e = s_e[jj];
            int s = s_s[jj];
            acc += g_attn[e * NHEAD + nh] * g_v[s * HID + c];
        }
        __syncthreads();
    }
    g_agg[n * HID + c] = acc;
}

// ---------------- residual + LayerNorm: h = LN(h + upd)*gamma + beta --------
__global__ void ln_kernel(const float* __restrict__ upd,
                          const float* __restrict__ gamma_l,
                          const float* __restrict__ beta_l) {
    int n = blockIdx.x;
    int t = threadIdx.x;   // 256
    float x = g_h[n * HID + t] + upd[n * HID + t];
    __shared__ float s1[8], s2[8];
    float a = x, b = x * x;
#pragma unroll
    for (int o = 16; o > 0; o >>= 1) {
        a += __shfl_down_sync(0xffffffffu, a, o);
        b += __shfl_down_sync(0xffffffffu, b, o);
    }
    int warp = t >> 5, lane = t & 31;
    if (lane == 0) { s1[warp] = a; s2[warp] = b; }
    __syncthreads();
    if (warp == 0) {
        a = (lane < 8) ? s1[lane] : 0.0f;
        b = (lane < 8) ? s2[lane] : 0.0f;
#pragma unroll
        for (int o = 4; o > 0; o >>= 1) {
            a += __shfl_down_sync(0xffffffffu, a, o);
            b += __shfl_down_sync(0xffffffffu, b, o);
        }
        if (lane == 0) { s1[0] = a; s2[0] = b; }
    }
    __syncthreads();
    float mu = s1[0] * (1.0f / HID);
    float var = s2[0] * (1.0f / HID) - mu * mu;
    g_h[n * HID + t] = (x - mu) * rsqrtf(var + 1e-5f) * gamma_l[t] + beta_l[t];
}

// ---------------- output head 2: out = hidden(N,128) @ W2(128,1) + b2 -------
__global__ void head2_kernel(const float* __restrict__ hidden,
                             const float* __restrict__ W2,
                             const float* __restrict__ b2,
                             float* __restrict__ out) {
    int gw = (blockIdx.x * blockDim.x + threadIdx.x) >> 5;
    int lane = threadIdx.x & 31;
    if (gw >= N_NODES) return;
    float acc = 0.0f;
#pragma unroll
    for (int i = 0; i < 4; i++) {
        int c = lane + i * 32;
        acc += hidden[gw * 128 + c] * W2[c];
    }
#pragma unroll
    for (int o = 16; o > 0; o >>= 1)
        acc += __shfl_down_sync(0xffffffffu, acc, o);
    if (lane == 0) out[gw] = acc + b2[0];
}

// ---------------- launch ----------------------------------------------------
extern "C" void kernel_launch(void* const* d_in, const int* in_sizes, int n_in,
                              void* d_out, int out_size) {
    const float* x         = (const float*)d_in[0];
    const float* edge_attr = (const float*)d_in[1];
    const float* W_in      = (const float*)d_in[2];
    const float* b_in      = (const float*)d_in[3];
    const float* Wq        = (const float*)d_in[4];
    const float* Wk        = (const float*)d_in[5];
    const float* Wv        = (const float*)d_in[6];
    const float* We        = (const float*)d_in[7];
    const float* Wo        = (const float*)d_in[8];
    const float* bo        = (const float*)d_in[9];
    const float* Wm        = (const float*)d_in[10];
    const float* bm        = (const float*)d_in[11];
    const float* gamma     = (const float*)d_in[12];
    const float* beta      = (const float*)d_in[13];
    const float* Wh1       = (const float*)d_in[14];
    const float* bh1       = (const float*)d_in[15];
    const float* Wh2       = (const float*)d_in[16];
    const float* bh2       = (const float*)d_in[17];
    const int*   ei_raw    = (const int*)d_in[18];

    float *ph, *pq, *pk, *pv, *pagg;
    cudaGetSymbolAddress((void**)&ph,   g_h);
    cudaGetSymbolAddress((void**)&pq,   g_q);
    cudaGetSymbolAddress((void**)&pk,   g_k);
    cudaGetSymbolAddress((void**)&pv,   g_v);
    cudaGetSymbolAddress((void**)&pagg, g_agg);

    const int NH_ELEMS = N_NODES * HID;

    // decode edge indices + build CSR (by dst)
    detect_idx<<<1, 256>>>(ei_raw);
    convert_idx<<<(N_EDGES + 255) / 256, 256>>>(ei_raw);
    zero_cnt<<<(N_NODES + 255) / 256, 256>>>();
    count_deg<<<(N_EDGES + 255) / 256, 256>>>();
    scan_rowstart<<<1, 1024>>>();
    copy_cursor<<<(N_NODES + 255) / 256, 256>>>();
    scatter_perm<<<(N_EDGES + 255) / 256, 256>>>();

    input_proj<<<(NH_ELEMS + 255) / 256, 256>>>(x, W_in, b_in);

    dim3 gridH(HID / 128, (N_NODES + 127) / 128);          // 2 x 391
    dim3 gridHead(1, (N_NODES + 127) / 128);               // M=128

    for (int l = 0; l < NLAYER; l++) {
        const float* Wq_l = Wq + l * HID * HID;
        const float* Wk_l = Wk + l * HID * HID;
        const float* Wv_l = Wv + l * HID * HID;
        const float* We_l = We + l * 3 * NHEAD;
        const float* Wo_l = Wo + l * HID * HID;
        const float* bo_l = bo + l * HID;
        const float* Wm_l = Wm + l * 2 * HID * HID;
        const float* bm_l = bm + l * HID;
        const float* ga_l = gamma + l * HID;
        const float* be_l = beta + l * HID;

        gemm128<<<gridH, 256>>>(ph, Wq_l, nullptr, pq, N_NODES, HID, HID, 0);
        gemm128<<<gridH, 256>>>(ph, Wk_l, nullptr, pk, N_NODES, HID, HID, 0);
        gemm128<<<gridH, 256>>>(ph, Wv_l, nullptr, pv, N_NODES, HID, HID, 0);

        zero_maxu<<<1, 1>>>();
        attn_kernel<<<(N_EDGES * NHEAD + 255) / 256, 256>>>(edge_attr, We_l);
        node_softmax<<<(N_NODES + 7) / 8, 256>>>();
        agg_gather<<<N_NODES, 256>>>();

        // aggO = agg @ Wo + bo   (reuse g_q)
        gemm128<<<gridH, 256>>>(pagg, Wo_l, bo_l, pq, N_NODES, HID, HID, 0);
        // upd = relu(concat([h, aggO]) @ Wm + bm)   (reuse g_k)
        gemm128_concat<<<gridH, 256>>>(ph, pq, Wm_l, bm_l, pk, N_NODES, HID);
        // h = LN(h + upd) * gamma + beta
        ln_kernel<<<N_NODES, 256>>>(pk, ga_l, be_l);
    }

    // head: hidden = relu(h @ Wh1 + bh1)  (reuse g_q), out = hidden @ Wh2 + bh2
    gemm128<<<gridHead, 256>>>(ph, Wh1, bh1, pq, N_NODES, HID, 128, 1);
    head2_kernel<<<(N_NODES * 32 + 255) / 256, 256>>>(pq, Wh2, bh2,
                                                      (float*)d_out);
}

// round 4
// speedup vs baseline: 3.8856x; 1.5871x over previous
#include <cuda_runtime.h>
#include <cuda_bf16.h>
#include <math.h>

#define N_NODES 50000
#define N_EDGES 800000
#define HID 256
#define NHEAD 8
#define HDIM 32
#define NLAYER 3
#define ATTN_SCALE 0.17677669529663687f   // 32^-0.5

// ---------------- scratch (static device globals; no allocs allowed) --------
__device__ float g_h[N_NODES * HID];
__device__ float g_q[N_NODES * HID];     // also reused: aggO, head hidden
__device__ float g_k[N_NODES * HID];     // also reused: upd
__device__ float g_v[N_NODES * HID];
__device__ float g_agg[N_NODES * HID];
__device__ float g_attn[N_EDGES * NHEAD];
__device__ unsigned int g_maxu;          // orderable-uint encoded global max
__device__ int g_src[N_EDGES];
__device__ int g_dst[N_EDGES];
__device__ int g_perm[N_EDGES];          // edges sorted by dst (CSR)
__device__ int g_rowstart[N_NODES + 1];
__device__ int g_cnt[N_NODES];
__device__ int g_cursor[N_NODES];
__device__ int g_is64;

__device__ __forceinline__ unsigned int f2o(float f) {
    unsigned int u = __float_as_uint(f);
    return (u & 0x80000000u) ? ~u : (u | 0x80000000u);
}
__device__ __forceinline__ float o2f(unsigned int u) {
    return (u & 0x80000000u) ? __uint_as_float(u & 0x7FFFFFFFu)
                             : __uint_as_float(~u);
}

// ---------------- index dtype detection + conversion ------------------------
__global__ void detect_idx(const int* __restrict__ raw) {
    __shared__ int any;
    if (threadIdx.x == 0) any = 0;
    __syncthreads();
    for (int i = threadIdx.x; i < 2048; i += blockDim.x)
        if (raw[2 * i + 1] != 0) any = 1;
    __syncthreads();
    if (threadIdx.x == 0) g_is64 = any ? 0 : 1;
}

__global__ void convert_idx(const int* __restrict__ raw) {
    int e = blockIdx.x * blockDim.x + threadIdx.x;
    if (e >= N_EDGES) return;
    int s, d;
    if (g_is64) {
        s = raw[2 * e];
        d = raw[2 * (N_EDGES + e)];
    } else {
        s = raw[e];
        d = raw[N_EDGES + e];
    }
    s = min(max(s, 0), N_NODES - 1);
    d = min(max(d, 0), N_NODES - 1);
    g_src[e] = s;
    g_dst[e] = d;
}

// ---------------- CSR build --------------------------------------------------
__global__ void zero_cnt() {
    int i = blockIdx.x * blockDim.x + threadIdx.x;
    if (i < N_NODES) g_cnt[i] = 0;
    if (i == 0) g_maxu = 0u;
}

__global__ void count_deg() {
    int e = blockIdx.x * blockDim.x + threadIdx.x;
    if (e >= N_EDGES) return;
    atomicAdd(&g_cnt[g_dst[e]], 1);
}

__global__ void scan_rowstart() {     // 1 block, 1024 threads
    __shared__ int sm[1024];
    int t = threadIdx.x;
    int run = 0;
    for (int base = 0; base < N_NODES; base += 1024) {
        int idx = base + t;
        int v = (idx < N_NODES) ? g_cnt[idx] : 0;
        sm[t] = v;
        __syncthreads();
        for (int off = 1; off < 1024; off <<= 1) {
            int x = (t >= off) ? sm[t - off] : 0;
            __syncthreads();
            sm[t] += x;
            __syncthreads();
        }
        if (idx < N_NODES) g_rowstart[idx] = run + sm[t] - v;
        run += sm[1023];
        __syncthreads();
    }
    if (t == 0) g_rowstart[N_NODES] = run;
}

__global__ void copy_cursor() {
    int i = blockIdx.x * blockDim.x + threadIdx.x;
    if (i < N_NODES) g_cursor[i] = g_rowstart[i];
}

__global__ void scatter_perm() {
    int e = blockIdx.x * blockDim.x + threadIdx.x;
    if (e >= N_EDGES) return;
    int pos = atomicAdd(&g_cursor[g_dst[e]], 1);
    g_perm[pos] = e;
}

__global__ void zero_maxu() { g_maxu = 0u; }

// ---------------- input projection: h = relu(x @ W_in + b_in) ---------------
__global__ void input_proj(const float* __restrict__ x,
                           const float* __restrict__ W,
                           const float* __restrict__ b) {
    int idx = blockIdx.x * blockDim.x + threadIdx.x;
    if (idx >= N_NODES * HID) return;
    int n = idx >> 8;
    int j = idx & 255;
    float acc = b[j];
#pragma unroll
    for (int f = 0; f < 10; f++) acc += x[n * 10 + f] * W[f * HID + j];
    g_h[idx] = fmaxf(acc, 0.0f);
}

// ---------------- tensor-core GEMM helpers -----------------------------------
__device__ __forceinline__ void mma_bf16(float* c, const unsigned* a,
                                         const unsigned* b) {
    asm volatile(
        "mma.sync.aligned.m16n8k16.row.col.f32.bf16.bf16.f32 "
        "{%0,%1,%2,%3}, {%4,%5,%6,%7}, {%8,%9}, {%0,%1,%2,%3};\n"
        : "+f"(c[0]), "+f"(c[1]), "+f"(c[2]), "+f"(c[3])
        : "r"(a[0]), "r"(a[1]), "r"(a[2]), "r"(a[3]), "r"(b[0]), "r"(b[1]));
}
__device__ __forceinline__ void ldsm4(unsigned* r, unsigned addr) {
    asm volatile(
        "ldmatrix.sync.aligned.m8n8.x4.shared.b16 {%0,%1,%2,%3}, [%4];\n"
        : "=r"(r[0]), "=r"(r[1]), "=r"(r[2]), "=r"(r[3]) : "r"(addr));
}
__device__ __forceinline__ void ldsm4t(unsigned* r, unsigned addr) {
    asm volatile(
        "ldmatrix.sync.aligned.m8n8.x4.trans.shared.b16 {%0,%1,%2,%3}, [%4];\n"
        : "=r"(r[0]), "=r"(r[1]), "=r"(r[2]), "=r"(r[3]) : "r"(addr));
}
__device__ __forceinline__ void split_bf16(float v, __nv_bfloat16& hi,
                                           __nv_bfloat16& lo) {
    hi = __float2bfloat16(v);
    lo = __float2bfloat16(v - __bfloat162float(hi));
}

// -------- split-precision tensor-core GEMM ----------------------------------
// C(Nr,M) = [relu]( A(Nr,K) @ B(K,M) + bias )
// A given as one or two row-major (Nr,256) fp32 arrays (A2!=null -> K=512 concat)
// Block tile 128x128, BK=32, 256 threads (8 warps as 4x2).
#define LDA 40
#define LDB 136
__global__ __launch_bounds__(256)
void gemm_tc(const float* __restrict__ A1,
             const float* __restrict__ A2,
             const float* __restrict__ B,
             const float* __restrict__ bias,
             float* __restrict__ C,
             int Nr, int K, int M, int relu) {
    __shared__ __align__(16) __nv_bfloat16 sAh[128][LDA];
    __shared__ __align__(16) __nv_bfloat16 sAl[128][LDA];
    __shared__ __align__(16) __nv_bfloat16 sBh[32][LDB];
    __shared__ __align__(16) __nv_bfloat16 sBl[32][LDB];

    int tid = threadIdx.x;
    int lane = tid & 31;
    int wid = tid >> 5;
    int warpM = wid & 3;          // 0..3 -> 32-row slab
    int warpN = wid >> 2;         // 0..1 -> 64-col slab
    int row0 = blockIdx.y * 128;
    int col0 = blockIdx.x * 128;

    float acc[2][8][4];
#pragma unroll
    for (int i = 0; i < 2; i++)
#pragma unroll
        for (int j = 0; j < 8; j++)
#pragma unroll
            for (int t = 0; t < 4; t++) acc[i][j][t] = 0.0f;

    // ldmatrix source addresses (per-lane, fixed per k-step pattern)
    int a_row = warpM * 32 + (lane & 15);       // + t*16
    int a_col8 = (lane >> 4) << 3;              // + ks*16
    int b_row = lane & 15;                      // + ks*16
    int b_col = warpN * 64 + ((lane >> 4) << 3);  // + g*16

    for (int k0 = 0; k0 < K; k0 += 32) {
        const float* Asrc = (k0 < 256) ? A1 : A2;
        int kb = k0 & 255;
        // ---- load + convert A tile (128 x 32) ----
#pragma unroll
        for (int i = 0; i < 4; i++) {
            int f = tid + i * 256;            // float4 id
            int m = f >> 3;
            int kq = (f & 7) * 4;
            int r = row0 + m;
            float4 v = make_float4(0.f, 0.f, 0.f, 0.f);
            if (r < Nr)
                v = *reinterpret_cast<const float4*>(&Asrc[r * 256 + kb + kq]);
            __nv_bfloat16 h0, l0, h1, l1, h2, l2, h3, l3;
            split_bf16(v.x, h0, l0);
            split_bf16(v.y, h1, l1);
            split_bf16(v.z, h2, l2);
            split_bf16(v.w, h3, l3);
            sAh[m][kq + 0] = h0; sAh[m][kq + 1] = h1;
            sAh[m][kq + 2] = h2; sAh[m][kq + 3] = h3;
            sAl[m][kq + 0] = l0; sAl[m][kq + 1] = l1;
            sAl[m][kq + 2] = l2; sAl[m][kq + 3] = l3;
        }
        // ---- load + convert B tile (32 x 128) ----
#pragma unroll
        for (int i = 0; i < 4; i++) {
            int f = tid + i * 256;
            int kk = f >> 5;
            int n = (f & 31) * 4;
            float4 v = *reinterpret_cast<const float4*>(
                &B[(k0 + kk) * M + col0 + n]);
            __nv_bfloat16 h0, l0, h1, l1, h2, l2, h3, l3;
            split_bf16(v.x, h0, l0);
            split_bf16(v.y, h1, l1);
            split_bf16(v.z, h2, l2);
            split_bf16(v.w, h3, l3);
            sBh[kk][n + 0] = h0; sBh[kk][n + 1] = h1;
            sBh[kk][n + 2] = h2; sBh[kk][n + 3] = h3;
            sBl[kk][n + 0] = l0; sBl[kk][n + 1] = l1;
            sBl[kk][n + 2] = l2; sBl[kk][n + 3] = l3;
        }
        __syncthreads();

#pragma unroll
        for (int ks = 0; ks < 2; ks++) {
            unsigned ah[2][4], al[2][4], bh[4][4], bl[4][4];
#pragma unroll
            for (int t = 0; t < 2; t++) {
                unsigned addr_h = (unsigned)__cvta_generic_to_shared(
                    &sAh[a_row + t * 16][ks * 16 + a_col8]);
                unsigned addr_l = (unsigned)__cvta_generic_to_shared(
                    &sAl[a_row + t * 16][ks * 16 + a_col8]);
                ldsm4(ah[t], addr_h);
                ldsm4(al[t], addr_l);
            }
#pragma unroll
            for (int g = 0; g < 4; g++) {
                unsigned addr_h = (unsigned)__cvta_generic_to_shared(
                    &sBh[ks * 16 + b_row][b_col + g * 16]);
                unsigned addr_l = (unsigned)__cvta_generic_to_shared(
                    &sBl[ks * 16 + b_row][b_col + g * 16]);
                ldsm4t(bh[g], addr_h);
                ldsm4t(bl[g], addr_l);
            }
#pragma unroll
            for (int i = 0; i < 2; i++) {
#pragma unroll
                for (int j = 0; j < 8; j++) {
                    mma_bf16(acc[i][j], ah[i], &bh[j >> 1][(j & 1) * 2]);
                    mma_bf16(acc[i][j], ah[i], &bl[j >> 1][(j & 1) * 2]);
                    mma_bf16(acc[i][j], al[i], &bh[j >> 1][(j & 1) * 2]);
                }
            }
        }
        __syncthreads();
    }

    // ---- epilogue ----
#pragma unroll
    for (int i = 0; i < 2; i++) {
        int rbase = row0 + warpM * 32 + i * 16 + (lane >> 2);
#pragma unroll
        for (int j = 0; j < 8; j++) {
            int c = col0 + warpN * 64 + j * 8 + (lane & 3) * 2;
            float b0 = bias ? bias[c] : 0.0f;
            float b1 = bias ? bias[c + 1] : 0.0f;
            float v0 = acc[i][j][0] + b0;
            float v1 = acc[i][j][1] + b1;
            float v2 = acc[i][j][2] + b0;
            float v3 = acc[i][j][3] + b1;
            if (relu) {
                v0 = fmaxf(v0, 0.f); v1 = fmaxf(v1, 0.f);
                v2 = fmaxf(v2, 0.f); v3 = fmaxf(v3, 0.f);
            }
            if (rbase < Nr)
                *reinterpret_cast<float2*>(&C[rbase * M + c]) =
                    make_float2(v0, v1);
            if (rbase + 8 < Nr)
                *reinterpret_cast<float2*>(&C[(rbase + 8) * M + c]) =
                    make_float2(v2, v3);
        }
    }
}

// ---------------- edge attention: attn = leaky(scale*<Q[d],K[s]> + eb) ------
__global__ void attn_kernel(const float* __restrict__ edge_attr,
                            const float* __restrict__ We_l) {
    int idx = blockIdx.x * blockDim.x + threadIdx.x;
    float a = -3.4e38f;
    if (idx < N_EDGES * NHEAD) {
        int e = idx >> 3;
        int nh = idx & 7;
        int s = g_src[e];
        int d = g_dst[e];
        const float4* q4 =
            reinterpret_cast<const float4*>(g_q + d * HID + nh * HDIM);
        const float4* k4 =
            reinterpret_cast<const float4*>(g_k + s * HID + nh * HDIM);
        float acc = 0.0f;
#pragma unroll
        for (int i = 0; i < 8; i++) {
            float4 qa = q4[i];
            float4 ka = k4[i];
            acc += qa.x * ka.x + qa.y * ka.y + qa.z * ka.z + qa.w * ka.w;
        }
        float eb = edge_attr[e * 3 + 0] * We_l[nh] +
                   edge_attr[e * 3 + 1] * We_l[8 + nh] +
                   edge_attr[e * 3 + 2] * We_l[16 + nh];
        a = acc * ATTN_SCALE + eb;
        a = (a > 0.0f) ? a : 0.2f * a;       // leaky_relu
        g_attn[idx] = a;
    }
    __shared__ float smax[8];
    float w = a;
#pragma unroll
    for (int o = 16; o > 0; o >>= 1)
        w = fmaxf(w, __shfl_down_sync(0xffffffffu, w, o));
    int warp = threadIdx.x >> 5, lane = threadIdx.x & 31;
    if (lane == 0) smax[warp] = w;
    __syncthreads();
    if (warp == 0) {
        w = (lane < 8) ? smax[lane] : -3.4e38f;
#pragma unroll
        for (int o = 4; o > 0; o >>= 1)
            w = fmaxf(w, __shfl_down_sync(0xffffffffu, w, o));
        if (lane == 0) atomicMax(&g_maxu, f2o(w));
    }
}

// ---------------- per-node softmax (CSR): one warp per node -----------------
__global__ void node_softmax() {
    int warp = threadIdx.x >> 5;
    int lane = threadIdx.x & 31;
    int n = blockIdx.x * 8 + warp;
    if (n >= N_NODES) return;
    int row = g_rowstart[n];
    int deg = g_rowstart[n + 1] - row;
    if (deg == 0) return;
    float m = o2f(g_maxu);
#pragma unroll
    for (int h = 0; h < NHEAD; h++) {
        float sum = 0.0f;
        for (int j = lane; j < deg; j += 32) {
            int e = g_perm[row + j];
            sum += __expf(g_attn[e * NHEAD + h] - m);
        }
#pragma unroll
        for (int o = 16; o > 0; o >>= 1)
            sum += __shfl_xor_sync(0xffffffffu, sum, o);
        float inv = 1.0f / fmaxf(sum, 1e-12f);
        for (int j = lane; j < deg; j += 32) {
            int e = g_perm[row + j];
            float v = __expf(g_attn[e * NHEAD + h] - m);
            g_attn[e * NHEAD + h] = v * inv;
        }
    }
}

// ---------------- weighted V aggregation (CSR gather, no atomics) -----------
__global__ void agg_gather() {
    __shared__ int s_e[256];
    __shared__ int s_s[256];
    int n = blockIdx.x;
    int c = threadIdx.x;
    int nh = c >> 5;
    int row = g_rowstart[n];
    int deg = g_rowstart[n + 1] - row;
    float acc = 0.0f;
    for (int chunk = 0; chunk < deg; chunk += 256) {
        int j = chunk + c;
        if (j < deg) {
            int e = g_perm[row + j];
            s_e[c] = e;
            s_s[c] = g_src[e];
        }
        __syncthreads();
        int cnt = min(256, deg - chunk);
        for (int jj = 0; jj < cnt; jj++) {
            int e = s_e[jj];
            int s = s_s[jj];
            acc += g_attn[e * NHEAD + nh] * g_v[s * HID + c];
        }
        __syncthreads();
    }
    g_agg[n * HID + c] = acc;
}

// ---------------- residual + LayerNorm: h = LN(h + upd)*gamma + beta --------
__global__ void ln_kernel(const float* __restrict__ upd,
                          const float* __restrict__ gamma_l,
                          const float* __restrict__ beta_l) {
    int n = blockIdx.x;
    int t = threadIdx.x;   // 256
    float x = g_h[n * HID + t] + upd[n * HID + t];
    __shared__ float s1[8], s2[8];
    float a = x, b = x * x;
#pragma unroll
    for (int o = 16; o > 0; o >>= 1) {
        a += __shfl_down_sync(0xffffffffu, a, o);
        b += __shfl_down_sync(0xffffffffu, b, o);
    }
    int warp = t >> 5, lane = t & 31;
    if (lane == 0) { s1[warp] = a; s2[warp] = b; }
    __syncthreads();
    if (warp == 0) {
        a = (lane < 8) ? s1[lane] : 0.0f;
        b = (lane < 8) ? s2[lane] : 0.0f;
#pragma unroll
        for (int o = 4; o > 0; o >>= 1) {
            a += __shfl_down_sync(0xffffffffu, a, o);
            b += __shfl_down_sync(0xffffffffu, b, o);
        }
        if (lane == 0) { s1[0] = a; s2[0] = b; }
    }
    __syncthreads();
    float mu = s1[0] * (1.0f / HID);
    float var = s2[0] * (1.0f / HID) - mu * mu;
    g_h[n * HID + t] = (x - mu) * rsqrtf(var + 1e-5f) * gamma_l[t] + beta_l[t];
}

// ---------------- output head 2: out = hidden(N,128) @ W2(128,1) + b2 -------
__global__ void head2_kernel(const float* __restrict__ hidden,
                             const float* __restrict__ W2,
                             const float* __restrict__ b2,
                             float* __restrict__ out) {
    int gw = (blockIdx.x * blockDim.x + threadIdx.x) >> 5;
    int lane = threadIdx.x & 31;
    if (gw >= N_NODES) return;
    float acc = 0.0f;
#pragma unroll
    for (int i = 0; i < 4; i++) {
        int c = lane + i * 32;
        acc += hidden[gw * 128 + c] * W2[c];
    }
#pragma unroll
    for (int o = 16; o > 0; o >>= 1)
        acc += __shfl_down_sync(0xffffffffu, acc, o);
    if (lane == 0) out[gw] = acc + b2[0];
}

// ---------------- launch ----------------------------------------------------
extern "C" void kernel_launch(void* const* d_in, const int* in_sizes, int n_in,
                              void* d_out, int out_size) {
    const float* x         = (const float*)d_in[0];
    const float* edge_attr = (const float*)d_in[1];
    const float* W_in      = (const float*)d_in[2];
    const float* b_in      = (const float*)d_in[3];
    const float* Wq        = (const float*)d_in[4];
    const float* Wk        = (const float*)d_in[5];
    const float* Wv        = (const float*)d_in[6];
    const float* We        = (const float*)d_in[7];
    const float* Wo        = (const float*)d_in[8];
    const float* bo        = (const float*)d_in[9];
    const float* Wm        = (const float*)d_in[10];
    const float* bm        = (const float*)d_in[11];
    const float* gamma     = (const float*)d_in[12];
    const float* beta      = (const float*)d_in[13];
    const float* Wh1       = (const float*)d_in[14];
    const float* bh1       = (const float*)d_in[15];
    const float* Wh2       = (const float*)d_in[16];
    const float* bh2       = (const float*)d_in[17];
    const int*   ei_raw    = (const int*)d_in[18];

    float *ph, *pq, *pk, *pv, *pagg;
    cudaGetSymbolAddress((void**)&ph,   g_h);
    cudaGetSymbolAddress((void**)&pq,   g_q);
    cudaGetSymbolAddress((void**)&pk,   g_k);
    cudaGetSymbolAddress((void**)&pv,   g_v);
    cudaGetSymbolAddress((void**)&pagg, g_agg);

    const int NH_ELEMS = N_NODES * HID;

    // decode edge indices + build CSR (by dst)
    detect_idx<<<1, 256>>>(ei_raw);
    convert_idx<<<(N_EDGES + 255) / 256, 256>>>(ei_raw);
    zero_cnt<<<(N_NODES + 255) / 256, 256>>>();
    count_deg<<<(N_EDGES + 255) / 256, 256>>>();
    scan_rowstart<<<1, 1024>>>();
    copy_cursor<<<(N_NODES + 255) / 256, 256>>>();
    scatter_perm<<<(N_EDGES + 255) / 256, 256>>>();

    input_proj<<<(NH_ELEMS + 255) / 256, 256>>>(x, W_in, b_in);

    dim3 gridH(2, (N_NODES + 127) / 128);      // M=256
    dim3 gridHead(1, (N_NODES + 127) / 128);   // M=128

    for (int l = 0; l < NLAYER; l++) {
        const float* Wq_l = Wq + l * HID * HID;
        const float* Wk_l = Wk + l * HID * HID;
        const float* Wv_l = Wv + l * HID * HID;
        const float* We_l = We + l * 3 * NHEAD;
        const float* Wo_l = Wo + l * HID * HID;
        const float* bo_l = bo + l * HID;
        const float* Wm_l = Wm + l * 2 * HID * HID;
        const float* bm_l = bm + l * HID;
        const float* ga_l = gamma + l * HID;
        const float* be_l = beta + l * HID;

        gemm_tc<<<gridH, 256>>>(ph, nullptr, Wq_l, nullptr, pq,
                                N_NODES, HID, HID, 0);
        gemm_tc<<<gridH, 256>>>(ph, nullptr, Wk_l, nullptr, pk,
                                N_NODES, HID, HID, 0);
        gemm_tc<<<gridH, 256>>>(ph, nullptr, Wv_l, nullptr, pv,
                                N_NODES, HID, HID, 0);

        zero_maxu<<<1, 1>>>();
        attn_kernel<<<(N_EDGES * NHEAD + 255) / 256, 256>>>(edge_attr, We_l);
        node_softmax<<<(N_NODES + 7) / 8, 256>>>();
        agg_gather<<<N_NODES, 256>>>();

        // aggO = agg @ Wo + bo   (reuse g_q)
        gemm_tc<<<gridH, 256>>>(pagg, nullptr, Wo_l, bo_l, pq,
                                N_NODES, HID, HID, 0);
        // upd = relu(concat([h, aggO]) @ Wm + bm)   (reuse g_k)
        gemm_tc<<<gridH, 256>>>(ph, pq, Wm_l, bm_l, pk,
                                N_NODES, 512, HID, 1);
        // h = LN(h + upd) * gamma + beta
        ln_kernel<<<N_NODES, 256>>>(pk, ga_l, be_l);
    }

    // head: hidden = relu(h @ Wh1 + bh1)  (reuse g_q), out = hidden @ Wh2 + bh2
    gemm_tc<<<gridHead, 256>>>(ph, nullptr, Wh1, bh1, pq,
                               N_NODES, HID, 128, 1);
    head2_kernel<<<(N_NODES * 32 + 255) / 256, 256>>>(pq, Wh2, bh2,
                                                      (float*)d_out);
}

// round 6
// speedup vs baseline: 4.9241x; 1.2673x over previous
#include <cuda_runtime.h>
#include <cuda_bf16.h>
#include <cuda_fp16.h>
#include <math.h>
#include <stdint.h>

#define N_NODES 50000
#define N_EDGES 800000
#define HID 256
#define NHEAD 8
#define HDIM 32
#define NLAYER 3
#define ATTN_SCALE 0.17677669529663687f   // 32^-0.5

// ---------------- scratch (static device globals; no allocs allowed) --------
__device__ float g_h[N_NODES * HID];
__device__ float g_q[N_NODES * HID];     // aggO / head hidden
__device__ float g_k[N_NODES * HID];     // upd
__device__ float g_v[N_NODES * HID];
__device__ float g_agg[N_NODES * HID];
__device__ __half g_qh[N_NODES * HID];   // Q in fp16
__device__ __half g_kh[N_NODES * HID];   // K in fp16
__device__ float g_attn[N_EDGES * NHEAD];
__device__ unsigned int g_maxu;
__device__ int g_src[N_EDGES];
__device__ int g_dst[N_EDGES];
__device__ int g_perm[N_EDGES];
__device__ int g_rowstart[N_NODES + 1];
__device__ int g_cnt[N_NODES];
__device__ int g_cursor[N_NODES];
__device__ int g_is64;

__device__ __forceinline__ unsigned int f2o(float f) {
    unsigned int u = __float_as_uint(f);
    return (u & 0x80000000u) ? ~u : (u | 0x80000000u);
}
__device__ __forceinline__ float o2f(unsigned int u) {
    return (u & 0x80000000u) ? __uint_as_float(u & 0x7FFFFFFFu)
                             : __uint_as_float(~u);
}

// ---------------- index dtype detection + conversion ------------------------
__global__ void detect_idx(const int* __restrict__ raw) {
    __shared__ int any;
    if (threadIdx.x == 0) any = 0;
    __syncthreads();
    for (int i = threadIdx.x; i < 2048; i += blockDim.x)
        if (raw[2 * i + 1] != 0) any = 1;
    __syncthreads();
    if (threadIdx.x == 0) g_is64 = any ? 0 : 1;
}

__global__ void convert_idx(const int* __restrict__ raw) {
    int e = blockIdx.x * blockDim.x + threadIdx.x;
    if (e >= N_EDGES) return;
    int s, d;
    if (g_is64) {
        s = raw[2 * e];
        d = raw[2 * (N_EDGES + e)];
    } else {
        s = raw[e];
        d = raw[N_EDGES + e];
    }
    s = min(max(s, 0), N_NODES - 1);
    d = min(max(d, 0), N_NODES - 1);
    g_src[e] = s;
    g_dst[e] = d;
}

// ---------------- CSR build --------------------------------------------------
__global__ void zero_cnt() {
    int i = blockIdx.x * blockDim.x + threadIdx.x;
    if (i < N_NODES) g_cnt[i] = 0;
    if (i == 0) g_maxu = 0u;
}

__global__ void count_deg() {
    int e = blockIdx.x * blockDim.x + threadIdx.x;
    if (e >= N_EDGES) return;
    atomicAdd(&g_cnt[g_dst[e]], 1);
}

__global__ void scan_rowstart() {     // 1 block, 1024 threads
    __shared__ int sm[1024];
    int t = threadIdx.x;
    int run = 0;
    for (int base = 0; base < N_NODES; base += 1024) {
        int idx = base + t;
        int v = (idx < N_NODES) ? g_cnt[idx] : 0;
        sm[t] = v;
        __syncthreads();
        for (int off = 1; off < 1024; off <<= 1) {
            int x = (t >= off) ? sm[t - off] : 0;
            __syncthreads();
            sm[t] += x;
            __syncthreads();
        }
        if (idx < N_NODES) g_rowstart[idx] = run + sm[t] - v;
        run += sm[1023];
        __syncthreads();
    }
    if (t == 0) g_rowstart[N_NODES] = run;
}

__global__ void copy_cursor() {
    int i = blockIdx.x * blockDim.x + threadIdx.x;
    if (i < N_NODES) g_cursor[i] = g_rowstart[i];
}

__global__ void scatter_perm() {
    int e = blockIdx.x * blockDim.x + threadIdx.x;
    if (e >= N_EDGES) return;
    int pos = atomicAdd(&g_cursor[g_dst[e]], 1);
    g_perm[pos] = e;
}

__global__ void zero_maxu() { g_maxu = 0u; }

// ---------------- input projection: h = relu(x @ W_in + b_in) ---------------
__global__ void input_proj(const float* __restrict__ x,
                           const float* __restrict__ W,
                           const float* __restrict__ b) {
    int idx = blockIdx.x * blockDim.x + threadIdx.x;
    if (idx >= N_NODES * HID) return;
    int n = idx >> 8;
    int j = idx & 255;
    float acc = b[j];
#pragma unroll
    for (int f = 0; f < 10; f++) acc += x[n * 10 + f] * W[f * HID + j];
    g_h[idx] = fmaxf(acc, 0.0f);
}

// ---------------- tensor-core GEMM helpers -----------------------------------
__device__ __forceinline__ void mma_bf16(float* c, const unsigned* a,
                                         const unsigned* b) {
    asm volatile(
        "mma.sync.aligned.m16n8k16.row.col.f32.bf16.bf16.f32 "
        "{%0,%1,%2,%3}, {%4,%5,%6,%7}, {%8,%9}, {%0,%1,%2,%3};\n"
        : "+f"(c[0]), "+f"(c[1]), "+f"(c[2]), "+f"(c[3])
        : "r"(a[0]), "r"(a[1]), "r"(a[2]), "r"(a[3]), "r"(b[0]), "r"(b[1]));
}
__device__ __forceinline__ void ldsm4(unsigned* r, unsigned addr) {
    asm volatile(
        "ldmatrix.sync.aligned.m8n8.x4.shared.b16 {%0,%1,%2,%3}, [%4];\n"
        : "=r"(r[0]), "=r"(r[1]), "=r"(r[2]), "=r"(r[3]) : "r"(addr));
}
__device__ __forceinline__ void ldsm4t(unsigned* r, unsigned addr) {
    asm volatile(
        "ldmatrix.sync.aligned.m8n8.x4.trans.shared.b16 {%0,%1,%2,%3}, [%4];\n"
        : "=r"(r[0]), "=r"(r[1]), "=r"(r[2]), "=r"(r[3]) : "r"(addr));
}
__device__ __forceinline__ void split_bf16(float v, __nv_bfloat16& hi,
                                           __nv_bfloat16& lo) {
    hi = __float2bfloat16(v);
    lo = __float2bfloat16(v - __bfloat162float(hi));
}

// -------- split-precision tensor-core multi-GEMM ----------------------------
// Computes up to 3 GEMMs in one launch (shared A):
//   out_g = [relu]( [A1|A2](Nr,Ktot) @ B_g(Ktot,Mout) + bias )
// grid.x enumerates (gemmIdx, colHalf) pairs: Mout=256 -> 2 col-blocks/gemm.
// Output per gemm: fp32 (C_g) or fp16 (H_g non-null).
#define LDA 40
#define LDB 136
__global__ __launch_bounds__(256)
void gemm_mma(const float* __restrict__ A1, const float* __restrict__ A2,
              const float* __restrict__ B0, const float* __restrict__ B1,
              const float* __restrict__ B2,
              const float* __restrict__ bias,
              float* __restrict__ C0, float* __restrict__ C1,
              float* __restrict__ C2,
              __half* __restrict__ H0, __half* __restrict__ H1,
              int Nr, int Ktot, int Mout, int relu) {
    __shared__ __align__(16) __nv_bfloat16 sAh[128][LDA];
    __shared__ __align__(16) __nv_bfloat16 sAl[128][LDA];
    __shared__ __align__(16) __nv_bfloat16 sBh[32][LDB];
    __shared__ __align__(16) __nv_bfloat16 sBl[32][LDB];

    int tid = threadIdx.x;
    int lane = tid & 31;
    int wid = tid >> 5;
    int warpM = wid & 3;
    int warpN = wid >> 2;
    int row0 = blockIdx.y * 128;

    int gi, chf;
    if (Mout == 256) { gi = blockIdx.x >> 1; chf = blockIdx.x & 1; }
    else             { gi = blockIdx.x;      chf = 0; }
    const float* B = (gi == 0) ? B0 : ((gi == 1) ? B1 : B2);
    float* Cf = (gi == 0) ? C0 : ((gi == 1) ? C1 : C2);
    __half* Hf = (gi == 0) ? H0 : ((gi == 1) ? H1 : nullptr);
    int col0 = chf * 128;

    float acc[2][8][4];
#pragma unroll
    for (int i = 0; i < 2; i++)
#pragma unroll
        for (int j = 0; j < 8; j++)
#pragma unroll
            for (int t = 0; t < 4; t++) acc[i][j][t] = 0.0f;

    int a_row = warpM * 32 + (lane & 15);
    int a_col8 = (lane >> 4) << 3;
    int b_row = lane & 15;
    int b_col = warpN * 64 + ((lane >> 4) << 3);

    int T = Ktot >> 5;
    float4 pa[4], pb[4];

    // preload tile 0
    {
        const float* Asrc = A1;
#pragma unroll
        for (int i = 0; i < 4; i++) {
            int f = tid + i * 256;
            int m = f >> 3, kq = (f & 7) * 4;
            int r = row0 + m;
            pa[i] = make_float4(0.f, 0.f, 0.f, 0.f);
            if (r < Nr)
                pa[i] = *reinterpret_cast<const float4*>(
                    &Asrc[(size_t)r * 256 + kq]);
        }
#pragma unroll
        for (int i = 0; i < 4; i++) {
            int f = tid + i * 256;
            int kk = f >> 5, n = (f & 31) * 4;
            pb[i] = *reinterpret_cast<const float4*>(
                &B[(size_t)kk * Mout + col0 + n]);
        }
    }

    for (int t = 0; t < T; t++) {
        // ---- store current tile regs -> smem (split hi/lo) ----
#pragma unroll
        for (int i = 0; i < 4; i++) {
            int f = tid + i * 256;
            int m = f >> 3, kq = (f & 7) * 4;
            __nv_bfloat16 h0, l0, h1, l1, h2, l2, h3, l3;
            split_bf16(pa[i].x, h0, l0);
            split_bf16(pa[i].y, h1, l1);
            split_bf16(pa[i].z, h2, l2);
            split_bf16(pa[i].w, h3, l3);
            sAh[m][kq + 0] = h0; sAh[m][kq + 1] = h1;
            sAh[m][kq + 2] = h2; sAh[m][kq + 3] = h3;
            sAl[m][kq + 0] = l0; sAl[m][kq + 1] = l1;
            sAl[m][kq + 2] = l2; sAl[m][kq + 3] = l3;
        }
#pragma unroll
        for (int i = 0; i < 4; i++) {
            int f = tid + i * 256;
            int kk = f >> 5, n = (f & 31) * 4;
            __nv_bfloat16 h0, l0, h1, l1, h2, l2, h3, l3;
            split_bf16(pb[i].x, h0, l0);
            split_bf16(pb[i].y, h1, l1);
            split_bf16(pb[i].z, h2, l2);
            split_bf16(pb[i].w, h3, l3);
            sBh[kk][n + 0] = h0; sBh[kk][n + 1] = h1;
            sBh[kk][n + 2] = h2; sBh[kk][n + 3] = h3;
            sBl[kk][n + 0] = l0; sBl[kk][n + 1] = l1;
            sBl[kk][n + 2] = l2; sBl[kk][n + 3] = l3;
        }
        __syncthreads();

        // ---- prefetch next tile (overlaps with MMA below) ----
        if (t + 1 < T) {
            int k0 = (t + 1) * 32;
            const float* Asrc = (k0 < 256) ? A1 : A2;
            int kb = k0 & 255;
#pragma unroll
            for (int i = 0; i < 4; i++) {
                int f = tid + i * 256;
                int m = f >> 3, kq = (f & 7) * 4;
                int r = row0 + m;
                pa[i] = make_float4(0.f, 0.f, 0.f, 0.f);
                if (r < Nr)
                    pa[i] = *reinterpret_cast<const float4*>(
                        &Asrc[(size_t)r * 256 + kb + kq]);
            }
#pragma unroll
            for (int i = 0; i < 4; i++) {
                int f = tid + i * 256;
                int kk = f >> 5, n = (f & 31) * 4;
                pb[i] = *reinterpret_cast<const float4*>(
                    &B[(size_t)(k0 + kk) * Mout + col0 + n]);
            }
        }

        // ---- MMA on current tile ----
#pragma unroll
        for (int ks = 0; ks < 2; ks++) {
            unsigned ah[2][4], al[2][4], bh[4][4], bl[4][4];
#pragma unroll
            for (int u = 0; u < 2; u++) {
                unsigned addr_h = (unsigned)__cvta_generic_to_shared(
                    &sAh[a_row + u * 16][ks * 16 + a_col8]);
                unsigned addr_l = (unsigned)__cvta_generic_to_shared(
                    &sAl[a_row + u * 16][ks * 16 + a_col8]);
                ldsm4(ah[u], addr_h);
                ldsm4(al[u], addr_l);
            }
#pragma unroll
            for (int g = 0; g < 4; g++) {
                unsigned addr_h = (unsigned)__cvta_generic_to_shared(
                    &sBh[ks * 16 + b_row][b_col + g * 16]);
                unsigned addr_l = (unsigned)__cvta_generic_to_shared(
                    &sBl[ks * 16 + b_row][b_col + g * 16]);
                ldsm4t(bh[g], addr_h);
                ldsm4t(bl[g], addr_l);
            }
#pragma unroll
            for (int i = 0; i < 2; i++) {
#pragma unroll
                for (int j = 0; j < 8; j++) {
                    mma_bf16(acc[i][j], ah[i], &bh[j >> 1][(j & 1) * 2]);
                    mma_bf16(acc[i][j], ah[i], &bl[j >> 1][(j & 1) * 2]);
                    mma_bf16(acc[i][j], al[i], &bh[j >> 1][(j & 1) * 2]);
                }
            }
        }
        __syncthreads();
    }

    // ---- epilogue ----
#pragma unroll
    for (int i = 0; i < 2; i++) {
        int rbase = row0 + warpM * 32 + i * 16 + (lane >> 2);
#pragma unroll
        for (int j = 0; j < 8; j++) {
            int c = col0 + warpN * 64 + j * 8 + (lane & 3) * 2;
            float b0 = bias ? bias[c] : 0.0f;
            float b1 = bias ? bias[c + 1] : 0.0f;
            float v0 = acc[i][j][0] + b0;
            float v1 = acc[i][j][1] + b1;
            float v2 = acc[i][j][2] + b0;
            float v3 = acc[i][j][3] + b1;
            if (relu) {
                v0 = fmaxf(v0, 0.f); v1 = fmaxf(v1, 0.f);
                v2 = fmaxf(v2, 0.f); v3 = fmaxf(v3, 0.f);
            }
            if (Hf) {
                if (rbase < Nr)
                    *reinterpret_cast<__half2*>(&Hf[(size_t)rbase * Mout + c]) =
                        __floats2half2_rn(v0, v1);
                if (rbase + 8 < Nr)
                    *reinterpret_cast<__half2*>(
                        &Hf[(size_t)(rbase + 8) * Mout + c]) =
                        __floats2half2_rn(v2, v3);
            } else {
                if (rbase < Nr)
                    *reinterpret_cast<float2*>(&Cf[(size_t)rbase * Mout + c]) =
                        make_float2(v0, v1);
                if (rbase + 8 < Nr)
                    *reinterpret_cast<float2*>(
                        &Cf[(size_t)(rbase + 8) * Mout + c]) =
                        make_float2(v2, v3);
            }
        }
    }
}

// ---------------- edge attention: attn = leaky(scale*<Q[d],K[s]> + eb) ------
__global__ void attn_kernel(const float* __restrict__ edge_attr,
                            const float* __restrict__ We_l) {
    int idx = blockIdx.x * blockDim.x + threadIdx.x;
    float a = -3.4e38f;
    if (idx < N_EDGES * NHEAD) {
        int e = idx >> 3;
        int nh = idx & 7;
        int s = g_src[e];
        int d = g_dst[e];
        const uint4* q4 =
            reinterpret_cast<const uint4*>(g_qh + d * HID + nh * HDIM);
        const uint4* k4 =
            reinterpret_cast<const uint4*>(g_kh + s * HID + nh * HDIM);
        float acc = 0.0f;
#pragma unroll
        for (int i = 0; i < 4; i++) {
            uint4 qa = q4[i];
            uint4 ka = k4[i];
            const __half2* qh = reinterpret_cast<const __half2*>(&qa);
            const __half2* kh = reinterpret_cast<const __half2*>(&ka);
#pragma unroll
            for (int j = 0; j < 4; j++) {
                float2 qf = __half22float2(qh[j]);
                float2 kf = __half22float2(kh[j]);
                acc = fmaf(qf.x, kf.x, acc);
                acc = fmaf(qf.y, kf.y, acc);
            }
        }
        float eb = edge_attr[e * 3 + 0] * We_l[nh] +
                   edge_attr[e * 3 + 1] * We_l[8 + nh] +
                   edge_attr[e * 3 + 2] * We_l[16 + nh];
        a = acc * ATTN_SCALE + eb;
        a = (a > 0.0f) ? a : 0.2f * a;       // leaky_relu
        g_attn[idx] = a;
    }
    __shared__ float smax[8];
    float w = a;
#pragma unroll
    for (int o = 16; o > 0; o >>= 1)
        w = fmaxf(w, __shfl_down_sync(0xffffffffu, w, o));
    int warp = threadIdx.x >> 5, lane = threadIdx.x & 31;
    if (lane == 0) smax[warp] = w;
    __syncthreads();
    if (warp == 0) {
        w = (lane < 8) ? smax[lane] : -3.4e38f;
#pragma unroll
        for (int o = 4; o > 0; o >>= 1)
            w = fmaxf(w, __shfl_down_sync(0xffffffffu, w, o));
        if (lane == 0) atomicMax(&g_maxu, f2o(w));
    }
}

// ---------------- per-node softmax (CSR): one warp per node -----------------
__global__ void node_softmax() {
    int warp = threadIdx.x >> 5;
    int lane = threadIdx.x & 31;
    int n = blockIdx.x * 8 + warp;
    if (n >= N_NODES) return;
    int row = g_rowstart[n];
    int deg = g_rowstart[n + 1] - row;
    if (deg == 0) return;
    float m = o2f(g_maxu);
#pragma unroll
    for (int h = 0; h < NHEAD; h++) {
        float sum = 0.0f;
        for (int j = lane; j < deg; j += 32) {
            int e = g_perm[row + j];
            sum += __expf(g_attn[e * NHEAD + h] - m);
        }
#pragma unroll
        for (int o = 16; o > 0; o >>= 1)
            sum += __shfl_xor_sync(0xffffffffu, sum, o);
        float inv = 1.0f / fmaxf(sum, 1e-12f);
        for (int j = lane; j < deg; j += 32) {
            int e = g_perm[row + j];
            float v = __expf(g_attn[e * NHEAD + h] - m);
            g_attn[e * NHEAD + h] = v * inv;
        }
    }
}

// ---------------- weighted V aggregation (CSR gather, no atomics) -----------
__global__ void agg_gather() {
    __shared__ int s_e[256];
    __shared__ int s_s[256];
    int n = blockIdx.x;
    int c = threadIdx.x;
    int nh = c >> 5;
    int row = g_rowstart[n];
    int deg = g_rowstart[n + 1] - row;
    float acc = 0.0f;
    for (int chunk = 0; chunk < deg; chunk += 256) {
        int j = chunk + c;
        if (j < deg) {
            int e = g_perm[row + j];
            s_e[c] = e;
            s_s[c] = g_src[e];
        }
        __syncthreads();
        int cnt = min(256, deg - chunk);
        for (int jj = 0; jj < cnt; jj++) {
            int e = s_e[jj];
            int s = s_s[jj];
            acc += g_attn[e * NHEAD + nh] * g_v[s * HID + c];
        }
        __syncthreads();
    }
    g_agg[n * HID + c] = acc;
}

// ---------------- residual + LayerNorm: h = LN(h + upd)*gamma + beta --------
__global__ void ln_kernel(const float* __restrict__ upd,
                          const float* __restrict__ gamma_l,
                          const float* __restrict__ beta_l) {
    int n = blockIdx.x;
    int t = threadIdx.x;   // 256
    float x = g_h[n * HID + t] + upd[n * HID + t];
    __shared__ float s1[8], s2[8];
    float a = x, b = x * x;
#pragma unroll
    for (int o = 16; o > 0; o >>= 1) {
        a += __shfl_down_sync(0xffffffffu, a, o);
        b += __shfl_down_sync(0xffffffffu, b, o);
    }
    int warp = t >> 5, lane = t & 31;
    if (lane == 0) { s1[warp] = a; s2[warp] = b; }
    __syncthreads();
    if (warp == 0) {
        a = (lane < 8) ? s1[lane] : 0.0f;
        b = (lane < 8) ? s2[lane] : 0.0f;
#pragma unroll
        for (int o = 4; o > 0; o >>= 1) {
            a += __shfl_down_sync(0xffffffffu, a, o);
            b += __shfl_down_sync(0xffffffffu, b, o);
        }
        if (lane == 0) { s1[0] = a; s2[0] = b; }
    }
    __syncthreads();
    float mu = s1[0] * (1.0f / HID);
    float var = s2[0] * (1.0f / HID) - mu * mu;
    g_h[n * HID + t] = (x - mu) * rsqrtf(var + 1e-5f) * gamma_l[t] + beta_l[t];
}

// ---------------- output head 2: out = hidden(N,128) @ W2(128,1) + b2 -------
__global__ void head2_kernel(const float* __restrict__ hidden,
                             const float* __restrict__ W2,
                             const float* __restrict__ b2,
                             float* __restrict__ out) {
    int gw = (blockIdx.x * blockDim.x + threadIdx.x) >> 5;
    int lane = threadIdx.x & 31;
    if (gw >= N_NODES) return;
    float acc = 0.0f;
#pragma unroll
    for (int i = 0; i < 4; i++) {
        int c = lane + i * 32;
        acc += hidden[gw * 128 + c] * W2[c];
    }
#pragma unroll
    for (int o = 16; o > 0; o >>= 1)
        acc += __shfl_down_sync(0xffffffffu, acc, o);
    if (lane == 0) out[gw] = acc + b2[0];
}

// ---------------- launch ----------------------------------------------------
extern "C" void kernel_launch(void* const* d_in, const int* in_sizes, int n_in,
                              void* d_out, int out_size) {
    const float* x         = (const float*)d_in[0];
    const float* edge_attr = (const float*)d_in[1];
    const float* W_in      = (const float*)d_in[2];
    const float* b_in      = (const float*)d_in[3];
    const float* Wq        = (const float*)d_in[4];
    const float* Wk        = (const float*)d_in[5];
    const float* Wv        = (const float*)d_in[6];
    const float* We        = (const float*)d_in[7];
    const float* Wo        = (const float*)d_in[8];
    const float* bo        = (const float*)d_in[9];
    const float* Wm        = (const float*)d_in[10];
    const float* bm        = (const float*)d_in[11];
    const float* gamma     = (const float*)d_in[12];
    const float* beta      = (const float*)d_in[13];
    const float* Wh1       = (const float*)d_in[14];
    const float* bh1       = (const float*)d_in[15];
    const float* Wh2       = (const float*)d_in[16];
    const float* bh2       = (const float*)d_in[17];
    const int*   ei_raw    = (const int*)d_in[18];

    float *ph, *pq, *pk, *pv, *pagg;
    __half *pqh, *pkh;
    cudaGetSymbolAddress((void**)&ph,   g_h);
    cudaGetSymbolAddress((void**)&pq,   g_q);
    cudaGetSymbolAddress((void**)&pk,   g_k);
    cudaGetSymbolAddress((void**)&pv,   g_v);
    cudaGetSymbolAddress((void**)&pagg, g_agg);
    cudaGetSymbolAddress((void**)&pqh,  g_qh);
    cudaGetSymbolAddress((void**)&pkh,  g_kh);

    const int NH_ELEMS = N_NODES * HID;

    // decode edge indices + build CSR (by dst)
    detect_idx<<<1, 256>>>(ei_raw);
    convert_idx<<<(N_EDGES + 255) / 256, 256>>>(ei_raw);
    zero_cnt<<<(N_NODES + 255) / 256, 256>>>();
    count_deg<<<(N_EDGES + 255) / 256, 256>>>();
    scan_rowstart<<<1, 1024>>>();
    copy_cursor<<<(N_NODES + 255) / 256, 256>>>();
    scatter_perm<<<(N_EDGES + 255) / 256, 256>>>();

    input_proj<<<(NH_ELEMS + 255) / 256, 256>>>(x, W_in, b_in);

    int rows = (N_NODES + 127) / 128;   // 391
    dim3 gridQKV(6, rows);
    dim3 grid1(2, rows);
    dim3 gridHead(1, rows);

    for (int l = 0; l < NLAYER; l++) {
        const float* Wq_l = Wq + l * HID * HID;
        const float* Wk_l = Wk + l * HID * HID;
        const float* Wv_l = Wv + l * HID * HID;
        const float* We_l = We + l * 3 * NHEAD;
        const float* Wo_l = Wo + l * HID * HID;
        const float* bo_l = bo + l * HID;
        const float* Wm_l = Wm + l * 2 * HID * HID;
        const float* bm_l = bm + l * HID;
        const float* ga_l = gamma + l * HID;
        const float* be_l = beta + l * HID;

        // fused QKV: Q->half, K->half, V->fp32
        gemm_mma<<<gridQKV, 256>>>(ph, nullptr, Wq_l, Wk_l, Wv_l, nullptr,
                                   nullptr, nullptr, pv, pqh, pkh,
                                   N_NODES, 256, 256, 0);

        zero_maxu<<<1, 1>>>();
        attn_kernel<<<(N_EDGES * NHEAD + 255) / 256, 256>>>(edge_attr, We_l);
        node_softmax<<<(N_NODES + 7) / 8, 256>>>();
        agg_gather<<<N_NODES, 256>>>();

        // aggO = agg @ Wo + bo   (fp32 -> g_q)
        gemm_mma<<<grid1, 256>>>(pagg, nullptr, Wo_l, Wo_l, Wo_l, bo_l,
                                 pq, pq, pq, nullptr, nullptr,
                                 N_NODES, 256, 256, 0);
        // upd = relu(concat([h, aggO]) @ Wm + bm)  (fp32 -> g_k)
        gemm_mma<<<grid1, 256>>>(ph, pq, Wm_l, Wm_l, Wm_l, bm_l,
                                 pk, pk, pk, nullptr, nullptr,
                                 N_NODES, 512, 256, 1);
        // h = LN(h + upd) * gamma + beta
        ln_kernel<<<N_NODES, 256>>>(pk, ga_l, be_l);
    }

    // head: hidden = relu(h @ Wh1 + bh1) -> g_q; out = hidden @ Wh2 + bh2
    gemm_mma<<<gridHead, 256>>>(ph, nullptr, Wh1, Wh1, Wh1, bh1,
                                pq, pq, pq, nullptr, nullptr,
                                N_NODES, 256, 128, 1);
    head2_kernel<<<(N_NODES * 32 + 255) / 256, 256>>>(pq, Wh2, bh2,
                                                      (float*)d_out);
}

// round 7
// speedup vs baseline: 4.9550x; 1.0063x over previous
#include <cuda_runtime.h>
#include <cuda_bf16.h>
#include <cuda_fp16.h>
#include <math.h>
#include <stdint.h>

#define N_NODES 50000
#define N_EDGES 800000
#define HID 256
#define NHEAD 8
#define HDIM 32
#define NLAYER 3
#define ATTN_SCALE 0.17677669529663687f   // 32^-0.5

typedef __nv_bfloat16 bf16;

// ---------------- scratch (static device globals; no allocs allowed) --------
__device__ float g_h[N_NODES * HID];       // fp32 h (LN residual)
__device__ bf16  g_h_hi[N_NODES * HID];    // h split for GEMM A
__device__ bf16  g_h_lo[N_NODES * HID];
__device__ bf16  g_agg_hi[N_NODES * HID];  // agg split (Wo GEMM A)
__device__ bf16  g_agg_lo[N_NODES * HID];
__device__ bf16  g_ao_hi[N_NODES * HID];   // aggO split (Wm GEMM A2)
__device__ bf16  g_ao_lo[N_NODES * HID];
__device__ float g_upd[N_NODES * HID];     // Wm output (fp32)
__device__ float g_hid[N_NODES * HID];     // head hidden (fp32, 128 used)
__device__ __half g_qh[N_NODES * HID];     // Q fp16
__device__ __half g_kh[N_NODES * HID];     // K fp16
__device__ __half g_vh[N_NODES * HID];     // V fp16
__device__ float g_attn[N_EDGES * NHEAD];
__device__ unsigned int g_maxu;
__device__ int g_src[N_EDGES];
__device__ int g_dst[N_EDGES];
__device__ int g_perm[N_EDGES];
__device__ int g_rowstart[N_NODES + 1];
__device__ int g_cnt[N_NODES];
__device__ int g_cursor[N_NODES];
__device__ int g_is64;

// pre-converted weights (bf16 hi/lo), offsets in elements:
// Wq:0(196608) Wk:196608 Wv:393216 Wo:589824 Wm:983040(393216) Wh1:1376256(32768)
#define OFF_WQ 0
#define OFF_WK 196608
#define OFF_WV 393216
#define OFF_WO 589824
#define OFF_WM 983040
#define OFF_WH1 1376256
#define W_TOTAL 1409024
__device__ bf16 g_w_hi[W_TOTAL];
__device__ bf16 g_w_lo[W_TOTAL];

__device__ __forceinline__ unsigned int f2o(float f) {
    unsigned int u = __float_as_uint(f);
    return (u & 0x80000000u) ? ~u : (u | 0x80000000u);
}
__device__ __forceinline__ float o2f(unsigned int u) {
    return (u & 0x80000000u) ? __uint_as_float(u & 0x7FFFFFFFu)
                             : __uint_as_float(~u);
}
__device__ __forceinline__ void split_bf16(float v, bf16& hi, bf16& lo) {
    hi = __float2bfloat16(v);
    lo = __float2bfloat16(v - __bfloat162float(hi));
}

// ---------------- index dtype detection + conversion ------------------------
__global__ void detect_idx(const int* __restrict__ raw) {
    __shared__ int any;
    if (threadIdx.x == 0) any = 0;
    __syncthreads();
    for (int i = threadIdx.x; i < 2048; i += blockDim.x)
        if (raw[2 * i + 1] != 0) any = 1;
    __syncthreads();
    if (threadIdx.x == 0) g_is64 = any ? 0 : 1;
}

__global__ void convert_idx(const int* __restrict__ raw) {
    int e = blockIdx.x * blockDim.x + threadIdx.x;
    if (e >= N_EDGES) return;
    int s, d;
    if (g_is64) {
        s = raw[2 * e];
        d = raw[2 * (N_EDGES + e)];
    } else {
        s = raw[e];
        d = raw[N_EDGES + e];
    }
    s = min(max(s, 0), N_NODES - 1);
    d = min(max(d, 0), N_NODES - 1);
    g_src[e] = s;
    g_dst[e] = d;
}

// ---------------- weight pre-conversion -------------------------------------
__global__ void convert_w(const float* __restrict__ src, int n, int off) {
    int i = blockIdx.x * blockDim.x + threadIdx.x;
    if (i >= n) return;
    bf16 hi, lo;
    split_bf16(src[i], hi, lo);
    g_w_hi[off + i] = hi;
    g_w_lo[off + i] = lo;
}

// ---------------- CSR build --------------------------------------------------
__global__ void zero_cnt() {
    int i = blockIdx.x * blockDim.x + threadIdx.x;
    if (i < N_NODES) g_cnt[i] = 0;
    if (i == 0) g_maxu = 0u;
}

__global__ void count_deg() {
    int e = blockIdx.x * blockDim.x + threadIdx.x;
    if (e >= N_EDGES) return;
    atomicAdd(&g_cnt[g_dst[e]], 1);
}

__global__ void scan_rowstart() {     // 1 block, 1024 threads
    __shared__ int sm[1024];
    int t = threadIdx.x;
    int run = 0;
    for (int base = 0; base < N_NODES; base += 1024) {
        int idx = base + t;
        int v = (idx < N_NODES) ? g_cnt[idx] : 0;
        sm[t] = v;
        __syncthreads();
        for (int off = 1; off < 1024; off <<= 1) {
            int x = (t >= off) ? sm[t - off] : 0;
            __syncthreads();
            sm[t] += x;
            __syncthreads();
        }
        if (idx < N_NODES) g_rowstart[idx] = run + sm[t] - v;
        run += sm[1023];
        __syncthreads();
    }
    if (t == 0) g_rowstart[N_NODES] = run;
}

__global__ void copy_cursor() {
    int i = blockIdx.x * blockDim.x + threadIdx.x;
    if (i < N_NODES) g_cursor[i] = g_rowstart[i];
}

__global__ void scatter_perm() {
    int e = blockIdx.x * blockDim.x + threadIdx.x;
    if (e >= N_EDGES) return;
    int pos = atomicAdd(&g_cursor[g_dst[e]], 1);
    g_perm[pos] = e;
}

__global__ void zero_maxu() { g_maxu = 0u; }

// ---------------- input projection: h = relu(x @ W_in + b_in) ---------------
__global__ void input_proj(const float* __restrict__ x,
                           const float* __restrict__ W,
                           const float* __restrict__ b) {
    int idx = blockIdx.x * blockDim.x + threadIdx.x;
    if (idx >= N_NODES * HID) return;
    int n = idx >> 8;
    int j = idx & 255;
    float acc = b[j];
#pragma unroll
    for (int f = 0; f < 10; f++) acc += x[n * 10 + f] * W[f * HID + j];
    float r = fmaxf(acc, 0.0f);
    g_h[idx] = r;
    bf16 hi, lo;
    split_bf16(r, hi, lo);
    g_h_hi[idx] = hi;
    g_h_lo[idx] = lo;
}

// ---------------- tensor-core GEMM helpers -----------------------------------
__device__ __forceinline__ void mma_bf16(float* c, const unsigned* a,
                                         const unsigned* b) {
    asm volatile(
        "mma.sync.aligned.m16n8k16.row.col.f32.bf16.bf16.f32 "
        "{%0,%1,%2,%3}, {%4,%5,%6,%7}, {%8,%9}, {%0,%1,%2,%3};\n"
        : "+f"(c[0]), "+f"(c[1]), "+f"(c[2]), "+f"(c[3])
        : "r"(a[0]), "r"(a[1]), "r"(a[2]), "r"(a[3]), "r"(b[0]), "r"(b[1]));
}
__device__ __forceinline__ void ldsm4(unsigned* r, unsigned addr) {
    asm volatile(
        "ldmatrix.sync.aligned.m8n8.x4.shared.b16 {%0,%1,%2,%3}, [%4];\n"
        : "=r"(r[0]), "=r"(r[1]), "=r"(r[2]), "=r"(r[3]) : "r"(addr));
}
__device__ __forceinline__ void ldsm4t(unsigned* r, unsigned addr) {
    asm volatile(
        "ldmatrix.sync.aligned.m8n8.x4.trans.shared.b16 {%0,%1,%2,%3}, [%4];\n"
        : "=r"(r[0]), "=r"(r[1]), "=r"(r[2]), "=r"(r[3]) : "r"(addr));
}

// -------- split-precision tensor-core multi-GEMM (pre-split inputs) ---------
// out_g = [relu]( [A|A2](Nr,Ktot) @ W[off_g](Ktot,Mout) + bias )
// All matrix inputs already split into bf16 hi/lo arrays.
// Output modes per gemm: fp16 (F_g), bf16-hilo (Ohi/Olo), else fp32 (Cf).
#define LDA 40
#define LDB 136
__global__ __launch_bounds__(256)
void gemm_mma(const bf16* __restrict__ Ahi, const bf16* __restrict__ Alo,
              const bf16* __restrict__ A2hi, const bf16* __restrict__ A2lo,
              int off0, int off1, int off2,
              const float* __restrict__ bias,
              float* __restrict__ Cf,
              __half* __restrict__ F0, __half* __restrict__ F1,
              __half* __restrict__ F2,
              bf16* __restrict__ Ohi, bf16* __restrict__ Olo,
              int Nr, int Ktot, int Mout, int relu) {
    __shared__ __align__(16) bf16 sAh[128][LDA];
    __shared__ __align__(16) bf16 sAl[128][LDA];
    __shared__ __align__(16) bf16 sBh[32][LDB];
    __shared__ __align__(16) bf16 sBl[32][LDB];

    int tid = threadIdx.x;
    int lane = tid & 31;
    int wid = tid >> 5;
    int warpM = wid & 3;
    int warpN = wid >> 2;
    int row0 = blockIdx.y * 128;

    int gi, chf;
    if (Mout == 256) { gi = blockIdx.x >> 1; chf = blockIdx.x & 1; }
    else             { gi = blockIdx.x;      chf = 0; }
    int boff = (gi == 0) ? off0 : ((gi == 1) ? off1 : off2);
    const bf16* Bh = g_w_hi + boff;
    const bf16* Bl = g_w_lo + boff;
    __half* Ff = (gi == 0) ? F0 : ((gi == 1) ? F1 : F2);
    int col0 = chf * 128;

    float acc[2][8][4];
#pragma unroll
    for (int i = 0; i < 2; i++)
#pragma unroll
        for (int j = 0; j < 8; j++)
#pragma unroll
            for (int t = 0; t < 4; t++) acc[i][j][t] = 0.0f;

    int a_row = warpM * 32 + (lane & 15);
    int a_col8 = (lane >> 4) << 3;
    int b_row = lane & 15;
    int b_col = warpN * 64 + ((lane >> 4) << 3);

    // fill mappings
    int a_m = tid >> 1;               // row 0..127
    int a_kq = (tid & 1) * 16;        // 16 k per thread
    int b_kk = tid >> 3;              // 0..31
    int b_n0 = (tid & 7) * 16;        // 0..112
    int grow = row0 + a_m;

    int T = Ktot >> 5;
    uint4 pah[2], pal[2], pbh[2], pbl[2];
    const uint4 z4 = make_uint4(0, 0, 0, 0);

    // preload tile 0
    {
        if (grow < Nr) {
            const uint4* ph4 = reinterpret_cast<const uint4*>(
                &Ahi[(size_t)grow * 256 + a_kq]);
            const uint4* pl4 = reinterpret_cast<const uint4*>(
                &Alo[(size_t)grow * 256 + a_kq]);
            pah[0] = ph4[0]; pah[1] = ph4[1];
            pal[0] = pl4[0]; pal[1] = pl4[1];
        } else {
            pah[0] = pah[1] = pal[0] = pal[1] = z4;
        }
        const uint4* qh4 = reinterpret_cast<const uint4*>(
            &Bh[(size_t)b_kk * Mout + col0 + b_n0]);
        const uint4* ql4 = reinterpret_cast<const uint4*>(
            &Bl[(size_t)b_kk * Mout + col0 + b_n0]);
        pbh[0] = qh4[0]; pbh[1] = qh4[1];
        pbl[0] = ql4[0]; pbl[1] = ql4[1];
    }

    for (int t = 0; t < T; t++) {
        // ---- store prefetched tile -> smem ----
        *reinterpret_cast<uint4*>(&sAh[a_m][a_kq]) = pah[0];
        *reinterpret_cast<uint4*>(&sAh[a_m][a_kq + 8]) = pah[1];
        *reinterpret_cast<uint4*>(&sAl[a_m][a_kq]) = pal[0];
        *reinterpret_cast<uint4*>(&sAl[a_m][a_kq + 8]) = pal[1];
        *reinterpret_cast<uint4*>(&sBh[b_kk][b_n0]) = pbh[0];
        *reinterpret_cast<uint4*>(&sBh[b_kk][b_n0 + 8]) = pbh[1];
        *reinterpret_cast<uint4*>(&sBl[b_kk][b_n0]) = pbl[0];
        *reinterpret_cast<uint4*>(&sBl[b_kk][b_n0 + 8]) = pbl[1];
        __syncthreads();

        // ---- prefetch next tile (overlaps MMA) ----
        if (t + 1 < T) {
            int k0 = (t + 1) * 32;
            const bf16* ah = (k0 < 256) ? Ahi : A2hi;
            const bf16* al = (k0 < 256) ? Alo : A2lo;
            int kb = k0 & 255;
            if (grow < Nr) {
                const uint4* ph4 = reinterpret_cast<const uint4*>(
                    &ah[(size_t)grow * 256 + kb + a_kq]);
                const uint4* pl4 = reinterpret_cast<const uint4*>(
                    &al[(size_t)grow * 256 + kb + a_kq]);
                pah[0] = ph4[0]; pah[1] = ph4[1];
                pal[0] = pl4[0]; pal[1] = pl4[1];
            } else {
                pah[0] = pah[1] = pal[0] = pal[1] = z4;
            }
            const uint4* qh4 = reinterpret_cast<const uint4*>(
                &Bh[(size_t)(k0 + b_kk) * Mout + col0 + b_n0]);
            const uint4* ql4 = reinterpret_cast<const uint4*>(
                &Bl[(size_t)(k0 + b_kk) * Mout + col0 + b_n0]);
            pbh[0] = qh4[0]; pbh[1] = qh4[1];
            pbl[0] = ql4[0]; pbl[1] = ql4[1];
        }

        // ---- MMA on current tile ----
#pragma unroll
        for (int ks = 0; ks < 2; ks++) {
            unsigned ah[2][4], al[2][4], bh[4][4], bl[4][4];
#pragma unroll
            for (int u = 0; u < 2; u++) {
                unsigned addr_h = (unsigned)__cvta_generic_to_shared(
                    &sAh[a_row + u * 16][ks * 16 + a_col8]);
                unsigned addr_l = (unsigned)__cvta_generic_to_shared(
                    &sAl[a_row + u * 16][ks * 16 + a_col8]);
                ldsm4(ah[u], addr_h);
                ldsm4(al[u], addr_l);
            }
#pragma unroll
            for (int g = 0; g < 4; g++) {
                unsigned addr_h = (unsigned)__cvta_generic_to_shared(
                    &sBh[ks * 16 + b_row][b_col + g * 16]);
                unsigned addr_l = (unsigned)__cvta_generic_to_shared(
                    &sBl[ks * 16 + b_row][b_col + g * 16]);
                ldsm4t(bh[g], addr_h);
                ldsm4t(bl[g], addr_l);
            }
#pragma unroll
            for (int i = 0; i < 2; i++) {
#pragma unroll
                for (int j = 0; j < 8; j++) {
                    mma_bf16(acc[i][j], ah[i], &bh[j >> 1][(j & 1) * 2]);
                    mma_bf16(acc[i][j], ah[i], &bl[j >> 1][(j & 1) * 2]);
                    mma_bf16(acc[i][j], al[i], &bh[j >> 1][(j & 1) * 2]);
                }
            }
        }
        __syncthreads();
    }

    // ---- epilogue ----
#pragma unroll
    for (int i = 0; i < 2; i++) {
        int rbase = row0 + warpM * 32 + i * 16 + (lane >> 2);
#pragma unroll
        for (int j = 0; j < 8; j++) {
            int c = col0 + warpN * 64 + j * 8 + (lane & 3) * 2;
            float b0 = bias ? bias[c] : 0.0f;
            float b1 = bias ? bias[c + 1] : 0.0f;
            float v0 = acc[i][j][0] + b0;
            float v1 = acc[i][j][1] + b1;
            float v2 = acc[i][j][2] + b0;
            float v3 = acc[i][j][3] + b1;
            if (relu) {
                v0 = fmaxf(v0, 0.f); v1 = fmaxf(v1, 0.f);
                v2 = fmaxf(v2, 0.f); v3 = fmaxf(v3, 0.f);
            }
            if (Ff) {
                if (rbase < Nr)
                    *reinterpret_cast<__half2*>(&Ff[(size_t)rbase * Mout + c]) =
                        __floats2half2_rn(v0, v1);
                if (rbase + 8 < Nr)
                    *reinterpret_cast<__half2*>(
                        &Ff[(size_t)(rbase + 8) * Mout + c]) =
                        __floats2half2_rn(v2, v3);
            } else if (Ohi) {
                bf16 h0, l0, h1, l1;
                if (rbase < Nr) {
                    split_bf16(v0, h0, l0);
                    split_bf16(v1, h1, l1);
                    __nv_bfloat162 ph, pl;
                    ph.x = h0; ph.y = h1; pl.x = l0; pl.y = l1;
                    *reinterpret_cast<__nv_bfloat162*>(
                        &Ohi[(size_t)rbase * Mout + c]) = ph;
                    *reinterpret_cast<__nv_bfloat162*>(
                        &Olo[(size_t)rbase * Mout + c]) = pl;
                }
                if (rbase + 8 < Nr) {
                    split_bf16(v2, h0, l0);
                    split_bf16(v3, h1, l1);
                    __nv_bfloat162 ph, pl;
                    ph.x = h0; ph.y = h1; pl.x = l0; pl.y = l1;
                    *reinterpret_cast<__nv_bfloat162*>(
                        &Ohi[(size_t)(rbase + 8) * Mout + c]) = ph;
                    *reinterpret_cast<__nv_bfloat162*>(
                        &Olo[(size_t)(rbase + 8) * Mout + c]) = pl;
                }
            } else {
                if (rbase < Nr)
                    *reinterpret_cast<float2*>(&Cf[(size_t)rbase * Mout + c]) =
                        make_float2(v0, v1);
                if (rbase + 8 < Nr)
                    *reinterpret_cast<float2*>(
                        &Cf[(size_t)(rbase + 8) * Mout + c]) =
                        make_float2(v2, v3);
            }
        }
    }
}

// ---------------- edge attention: attn = leaky(scale*<Q[d],K[s]> + eb) ------
__global__ void attn_kernel(const float* __restrict__ edge_attr,
                            const float* __restrict__ We_l) {
    int idx = blockIdx.x * blockDim.x + threadIdx.x;
    float a = -3.4e38f;
    if (idx < N_EDGES * NHEAD) {
        int e = idx >> 3;
        int nh = idx & 7;
        int s = g_src[e];
        int d = g_dst[e];
        const uint4* q4 =
            reinterpret_cast<const uint4*>(g_qh + d * HID + nh * HDIM);
        const uint4* k4 =
            reinterpret_cast<const uint4*>(g_kh + s * HID + nh * HDIM);
        float acc = 0.0f;
#pragma unroll
        for (int i = 0; i < 4; i++) {
            uint4 qa = q4[i];
            uint4 ka = k4[i];
            const __half2* qh = reinterpret_cast<const __half2*>(&qa);
            const __half2* kh = reinterpret_cast<const __half2*>(&ka);
#pragma unroll
            for (int j = 0; j < 4; j++) {
                float2 qf = __half22float2(qh[j]);
                float2 kf = __half22float2(kh[j]);
                acc = fmaf(qf.x, kf.x, acc);
                acc = fmaf(qf.y, kf.y, acc);
            }
        }
        float eb = edge_attr[e * 3 + 0] * We_l[nh] +
                   edge_attr[e * 3 + 1] * We_l[8 + nh] +
                   edge_attr[e * 3 + 2] * We_l[16 + nh];
        a = acc * ATTN_SCALE + eb;
        a = (a > 0.0f) ? a : 0.2f * a;       // leaky_relu
        g_attn[idx] = a;
    }
    __shared__ float smax[8];
    float w = a;
#pragma unroll
    for (int o = 16; o > 0; o >>= 1)
        w = fmaxf(w, __shfl_down_sync(0xffffffffu, w, o));
    int warp = threadIdx.x >> 5, lane = threadIdx.x & 31;
    if (lane == 0) smax[warp] = w;
    __syncthreads();
    if (warp == 0) {
        w = (lane < 8) ? smax[lane] : -3.4e38f;
#pragma unroll
        for (int o = 4; o > 0; o >>= 1)
            w = fmaxf(w, __shfl_down_sync(0xffffffffu, w, o));
        if (lane == 0) atomicMax(&g_maxu, f2o(w));
    }
}

// ---------------- per-node softmax (CSR): one warp per node -----------------
__global__ void node_softmax() {
    int warp = threadIdx.x >> 5;
    int lane = threadIdx.x & 31;
    int n = blockIdx.x * 8 + warp;
    if (n >= N_NODES) return;
    int row = g_rowstart[n];
    int deg = g_rowstart[n + 1] - row;
    if (deg == 0) return;
    float m = o2f(g_maxu);
#pragma unroll
    for (int h = 0; h < NHEAD; h++) {
        float sum = 0.0f;
        for (int j = lane; j < deg; j += 32) {
            int e = g_perm[row + j];
            sum += __expf(g_attn[e * NHEAD + h] - m);
        }
#pragma unroll
        for (int o = 16; o > 0; o >>= 1)
            sum += __shfl_xor_sync(0xffffffffu, sum, o);
        float inv = 1.0f / fmaxf(sum, 1e-12f);
        for (int j = lane; j < deg; j += 32) {
            int e = g_perm[row + j];
            float v = __expf(g_attn[e * NHEAD + h] - m);
            g_attn[e * NHEAD + h] = v * inv;
        }
    }
}

// ---------------- weighted V aggregation (CSR gather, fp16 V) ---------------
__global__ void agg_gather() {
    __shared__ int s_e[256];
    __shared__ int s_s[256];
    int n = blockIdx.x;
    int c = threadIdx.x;
    int nh = c >> 5;
    int row = g_rowstart[n];
    int deg = g_rowstart[n + 1] - row;
    float acc = 0.0f;
    for (int chunk = 0; chunk < deg; chunk += 256) {
        int j = chunk + c;
        if (j < deg) {
            int e = g_perm[row + j];
            s_e[c] = e;
            s_s[c] = g_src[e];
        }
        __syncthreads();
        int cnt = min(256, deg - chunk);
        for (int jj = 0; jj < cnt; jj++) {
            int e = s_e[jj];
            int s = s_s[jj];
            acc += g_attn[e * NHEAD + nh] * __half2float(g_vh[s * HID + c]);
        }
        __syncthreads();
    }
    bf16 hi, lo;
    split_bf16(acc, hi, lo);
    g_agg_hi[n * HID + c] = hi;
    g_agg_lo[n * HID + c] = lo;
}

// ---------------- residual + LayerNorm: h = LN(h + upd)*gamma + beta --------
__global__ void ln_kernel(const float* __restrict__ upd,
                          const float* __restrict__ gamma_l,
                          const float* __restrict__ beta_l) {
    int n = blockIdx.x;
    int t = threadIdx.x;   // 256
    float x = g_h[n * HID + t] + upd[n * HID + t];
    __shared__ float s1[8], s2[8];
    float a = x, b = x * x;
#pragma unroll
    for (int o = 16; o > 0; o >>= 1) {
        a += __shfl_down_sync(0xffffffffu, a, o);
        b += __shfl_down_sync(0xffffffffu, b, o);
    }
    int warp = t >> 5, lane = t & 31;
    if (lane == 0) { s1[warp] = a; s2[warp] = b; }
    __syncthreads();
    if (warp == 0) {
        a = (lane < 8) ? s1[lane] : 0.0f;
        b = (lane < 8) ? s2[lane] : 0.0f;
#pragma unroll
        for (int o = 4; o > 0; o >>= 1) {
            a += __shfl_down_sync(0xffffffffu, a, o);
            b += __shfl_down_sync(0xffffffffu, b, o);
        }
        if (lane == 0) { s1[0] = a; s2[0] = b; }
    }
    __syncthreads();
    float mu = s1[0] * (1.0f / HID);
    float var = s2[0] * (1.0f / HID) - mu * mu;
    float r = (x - mu) * rsqrtf(var + 1e-5f) * gamma_l[t] + beta_l[t];
    g_h[n * HID + t] = r;
    bf16 hi, lo;
    split_bf16(r, hi, lo);
    g_h_hi[n * HID + t] = hi;
    g_h_lo[n * HID + t] = lo;
}

// ---------------- output head 2: out = hidden(N,128) @ W2(128,1) + b2 -------
__global__ void head2_kernel(const float* __restrict__ hidden,
                             const float* __restrict__ W2,
                             const float* __restrict__ b2,
                             float* __restrict__ out) {
    int gw = (blockIdx.x * blockDim.x + threadIdx.x) >> 5;
    int lane = threadIdx.x & 31;
    if (gw >= N_NODES) return;
    float acc = 0.0f;
#pragma unroll
    for (int i = 0; i < 4; i++) {
        int c = lane + i * 32;
        acc += hidden[gw * 128 + c] * W2[c];
    }
#pragma unroll
    for (int o = 16; o > 0; o >>= 1)
        acc += __shfl_down_sync(0xffffffffu, acc, o);
    if (lane == 0) out[gw] = acc + b2[0];
}

// ---------------- launch ----------------------------------------------------
extern "C" void kernel_launch(void* const* d_in, const int* in_sizes, int n_in,
                              void* d_out, int out_size) {
    const float* x         = (const float*)d_in[0];
    const float* edge_attr = (const float*)d_in[1];
    const float* W_in      = (const float*)d_in[2];
    const float* b_in      = (const float*)d_in[3];
    const float* Wq        = (const float*)d_in[4];
    const float* Wk        = (const float*)d_in[5];
    const float* Wv        = (const float*)d_in[6];
    const float* We        = (const float*)d_in[7];
    const float* Wo        = (const float*)d_in[8];
    const float* bo        = (const float*)d_in[9];
    const float* Wm        = (const float*)d_in[10];
    const float* bm        = (const float*)d_in[11];
    const float* gamma     = (const float*)d_in[12];
    const float* beta      = (const float*)d_in[13];
    const float* Wh1       = (const float*)d_in[14];
    const float* bh1       = (const float*)d_in[15];
    const float* Wh2       = (const float*)d_in[16];
    const float* bh2       = (const float*)d_in[17];
    const int*   ei_raw    = (const int*)d_in[18];

    bf16 *phhi, *phlo, *pagghi, *pagglo, *paohi, *paolo;
    float *pupd, *phid;
    __half *pqh, *pkh, *pvh;
    cudaGetSymbolAddress((void**)&phhi,   g_h_hi);
    cudaGetSymbolAddress((void**)&phlo,   g_h_lo);
    cudaGetSymbolAddress((void**)&pagghi, g_agg_hi);
    cudaGetSymbolAddress((void**)&pagglo, g_agg_lo);
    cudaGetSymbolAddress((void**)&paohi,  g_ao_hi);
    cudaGetSymbolAddress((void**)&paolo,  g_ao_lo);
    cudaGetSymbolAddress((void**)&pupd,   g_upd);
    cudaGetSymbolAddress((void**)&phid,   g_hid);
    cudaGetSymbolAddress((void**)&pqh,    g_qh);
    cudaGetSymbolAddress((void**)&pkh,    g_kh);
    cudaGetSymbolAddress((void**)&pvh,    g_vh);

    const int NH_ELEMS = N_NODES * HID;

    // decode edge indices + build CSR (by dst)
    detect_idx<<<1, 256>>>(ei_raw);
    convert_idx<<<(N_EDGES + 255) / 256, 256>>>(ei_raw);
    zero_cnt<<<(N_NODES + 255) / 256, 256>>>();
    count_deg<<<(N_EDGES + 255) / 256, 256>>>();
    scan_rowstart<<<1, 1024>>>();
    copy_cursor<<<(N_NODES + 255) / 256, 256>>>();
    scatter_perm<<<(N_EDGES + 255) / 256, 256>>>();

    // pre-convert weights to bf16 hi/lo
    convert_w<<<(196608 + 255) / 256, 256>>>(Wq, 196608, OFF_WQ);
    convert_w<<<(196608 + 255) / 256, 256>>>(Wk, 196608, OFF_WK);
    convert_w<<<(196608 + 255) / 256, 256>>>(Wv, 196608, OFF_WV);
    convert_w<<<(196608 + 255) / 256, 256>>>(Wo, 196608, OFF_WO);
    convert_w<<<(393216 + 255) / 256, 256>>>(Wm, 393216, OFF_WM);
    convert_w<<<(32768 + 255) / 256, 256>>>(Wh1, 32768, OFF_WH1);

    input_proj<<<(NH_ELEMS + 255) / 256, 256>>>(x, W_in, b_in);

    int rows = (N_NODES + 127) / 128;   // 391
    dim3 gridQKV(6, rows);
    dim3 grid1(2, rows);
    dim3 gridHead(1, rows);

    for (int l = 0; l < NLAYER; l++) {
        int offQ = OFF_WQ + l * 65536;
        int offK = OFF_WK + l * 65536;
        int offV = OFF_WV + l * 65536;
        int offO = OFF_WO + l * 65536;
        int offM = OFF_WM + l * 131072;
        const float* We_l = We + l * 3 * NHEAD;
        const float* bo_l = bo + l * HID;
        const float* bm_l = bm + l * HID;
        const float* ga_l = gamma + l * HID;
        const float* be_l = beta + l * HID;

        // fused QKV: all fp16 out
        gemm_mma<<<gridQKV, 256>>>(phhi, phlo, nullptr, nullptr,
                                   offQ, offK, offV, nullptr,
                                   nullptr, pqh, pkh, pvh, nullptr, nullptr,
                                   N_NODES, 256, 256, 0);

        zero_maxu<<<1, 1>>>();
        attn_kernel<<<(N_EDGES * NHEAD + 255) / 256, 256>>>(edge_attr, We_l);
        node_softmax<<<(N_NODES + 7) / 8, 256>>>();
        agg_gather<<<N_NODES, 256>>>();

        // aggO = agg @ Wo + bo  -> bf16 hilo
        gemm_mma<<<grid1, 256>>>(pagghi, pagglo, nullptr, nullptr,
                                 offO, offO, offO, bo_l,
                                 nullptr, nullptr, nullptr, nullptr,
                                 paohi, paolo,
                                 N_NODES, 256, 256, 0);
        // upd = relu(concat([h, aggO]) @ Wm + bm)  -> fp32
        gemm_mma<<<grid1, 256>>>(phhi, phlo, paohi, paolo,
                                 offM, offM, offM, bm_l,
                                 pupd, nullptr, nullptr, nullptr,
                                 nullptr, nullptr,
                                 N_NODES, 512, 256, 1);
        // h = LN(h + upd) * gamma + beta  (+ hilo refresh)
        ln_kernel<<<N_NODES, 256>>>(pupd, ga_l, be_l);
    }

    // head: hidden = relu(h @ Wh1 + bh1) -> fp32; out = hidden @ Wh2 + bh2
    gemm_mma<<<gridHead, 256>>>(phhi, phlo, nullptr, nullptr,
                                OFF_WH1, OFF_WH1, OFF_WH1, bh1,
                                phid, nullptr, nullptr, nullptr,
                                nullptr, nullptr,
                                N_NODES, 256, 128, 1);
    head2_kernel<<<(N_NODES * 32 + 255) / 256, 256>>>(phid, Wh2, bh2,
                                                      (float*)d_out);
}

// round 8
// speedup vs baseline: 5.4547x; 1.1008x over previous
#include <cuda_runtime.h>
#include <cuda_bf16.h>
#include <cuda_fp16.h>
#include <math.h>
#include <stdint.h>

#define N_NODES 50000
#define N_EDGES 800000
#define HID 256
#define NHEAD 8
#define HDIM 32
#define NLAYER 3
#define ATTN_SCALE 0.17677669529663687f   // 32^-0.5

typedef __nv_bfloat16 bf16;

// ---------------- scratch (static device globals; no allocs allowed) --------
__device__ float g_h[N_NODES * HID];       // fp32 h (LN residual)
__device__ bf16  g_h_hi[N_NODES * HID];    // h split for GEMM A
__device__ bf16  g_h_lo[N_NODES * HID];
__device__ bf16  g_agg_hi[N_NODES * HID];  // agg split (Wo GEMM A)
__device__ bf16  g_agg_lo[N_NODES * HID];
__device__ bf16  g_ao_hi[N_NODES * HID];   // aggO split (Wm GEMM A2)
__device__ bf16  g_ao_lo[N_NODES * HID];
__device__ float g_upd[N_NODES * HID];     // Wm output (fp32)
__device__ float g_hid[N_NODES * HID];     // head hidden (fp32, 128 used)
__device__ __half g_qh[N_NODES * HID];     // Q fp16
__device__ __half g_kh[N_NODES * HID];     // K fp16
__device__ __half g_vh[N_NODES * HID];     // V fp16
__device__ float g_attn[N_EDGES * NHEAD];
__device__ float g_inv[N_NODES * NHEAD];   // 1/softmax-sum per (node,head)
__device__ unsigned int g_maxu;
__device__ int g_src[N_EDGES];
__device__ int g_dst[N_EDGES];
__device__ int g_perm[N_EDGES];
__device__ int g_rowstart[N_NODES + 1];
__device__ int g_cnt[N_NODES];
__device__ int g_cursor[N_NODES];
__device__ int g_is64;

// pre-converted weights (bf16 hi/lo)
#define OFF_WQ 0
#define OFF_WK 196608
#define OFF_WV 393216
#define OFF_WO 589824
#define OFF_WM 983040
#define OFF_WH1 1376256
#define W_TOTAL 1409024
__device__ bf16 g_w_hi[W_TOTAL];
__device__ bf16 g_w_lo[W_TOTAL];

__device__ __forceinline__ unsigned int f2o(float f) {
    unsigned int u = __float_as_uint(f);
    return (u & 0x80000000u) ? ~u : (u | 0x80000000u);
}
__device__ __forceinline__ float o2f(unsigned int u) {
    return (u & 0x80000000u) ? __uint_as_float(u & 0x7FFFFFFFu)
                             : __uint_as_float(~u);
}
__device__ __forceinline__ void split_bf16(float v, bf16& hi, bf16& lo) {
    hi = __float2bfloat16(v);
    lo = __float2bfloat16(v - __bfloat162float(hi));
}

// ---------------- index dtype detection + conversion ------------------------
__global__ void detect_idx(const int* __restrict__ raw) {
    __shared__ int any;
    if (threadIdx.x == 0) any = 0;
    __syncthreads();
    for (int i = threadIdx.x; i < 2048; i += blockDim.x)
        if (raw[2 * i + 1] != 0) any = 1;
    __syncthreads();
    if (threadIdx.x == 0) g_is64 = any ? 0 : 1;
}

__global__ void convert_idx(const int* __restrict__ raw) {
    int e = blockIdx.x * blockDim.x + threadIdx.x;
    if (e >= N_EDGES) return;
    int s, d;
    if (g_is64) {
        s = raw[2 * e];
        d = raw[2 * (N_EDGES + e)];
    } else {
        s = raw[e];
        d = raw[N_EDGES + e];
    }
    s = min(max(s, 0), N_NODES - 1);
    d = min(max(d, 0), N_NODES - 1);
    g_src[e] = s;
    g_dst[e] = d;
}

// ---------------- weight pre-conversion -------------------------------------
__global__ void convert_w(const float* __restrict__ src, int n, int off) {
    int i = blockIdx.x * blockDim.x + threadIdx.x;
    if (i >= n) return;
    bf16 hi, lo;
    split_bf16(src[i], hi, lo);
    g_w_hi[off + i] = hi;
    g_w_lo[off + i] = lo;
}

// ---------------- CSR build --------------------------------------------------
__global__ void zero_cnt() {
    int i = blockIdx.x * blockDim.x + threadIdx.x;
    if (i < N_NODES) g_cnt[i] = 0;
    if (i == 0) g_maxu = 0u;
}

__global__ void count_deg() {
    int e = blockIdx.x * blockDim.x + threadIdx.x;
    if (e >= N_EDGES) return;
    atomicAdd(&g_cnt[g_dst[e]], 1);
}

__global__ void scan_rowstart() {     // 1 block, 1024 threads
    __shared__ int sm[1024];
    int t = threadIdx.x;
    int run = 0;
    for (int base = 0; base < N_NODES; base += 1024) {
        int idx = base + t;
        int v = (idx < N_NODES) ? g_cnt[idx] : 0;
        sm[t] = v;
        __syncthreads();
        for (int off = 1; off < 1024; off <<= 1) {
            int x = (t >= off) ? sm[t - off] : 0;
            __syncthreads();
            sm[t] += x;
            __syncthreads();
        }
        if (idx < N_NODES) g_rowstart[idx] = run + sm[t] - v;
        run += sm[1023];
        __syncthreads();
    }
    if (t == 0) g_rowstart[N_NODES] = run;
}

__global__ void copy_cursor() {
    int i = blockIdx.x * blockDim.x + threadIdx.x;
    if (i < N_NODES) g_cursor[i] = g_rowstart[i];
}

__global__ void scatter_perm() {
    int e = blockIdx.x * blockDim.x + threadIdx.x;
    if (e >= N_EDGES) return;
    int pos = atomicAdd(&g_cursor[g_dst[e]], 1);
    g_perm[pos] = e;
}

__global__ void zero_maxu() { g_maxu = 0u; }

// ---------------- input projection: h = relu(x @ W_in + b_in) ---------------
__global__ void input_proj(const float* __restrict__ x,
                           const float* __restrict__ W,
                           const float* __restrict__ b) {
    int idx = blockIdx.x * blockDim.x + threadIdx.x;
    if (idx >= N_NODES * HID) return;
    int n = idx >> 8;
    int j = idx & 255;
    float acc = b[j];
#pragma unroll
    for (int f = 0; f < 10; f++) acc += x[n * 10 + f] * W[f * HID + j];
    float r = fmaxf(acc, 0.0f);
    g_h[idx] = r;
    bf16 hi, lo;
    split_bf16(r, hi, lo);
    g_h_hi[idx] = hi;
    g_h_lo[idx] = lo;
}

// ---------------- tensor-core GEMM helpers -----------------------------------
__device__ __forceinline__ void mma_bf16(float* c, const unsigned* a,
                                         const unsigned* b) {
    asm volatile(
        "mma.sync.aligned.m16n8k16.row.col.f32.bf16.bf16.f32 "
        "{%0,%1,%2,%3}, {%4,%5,%6,%7}, {%8,%9}, {%0,%1,%2,%3};\n"
        : "+f"(c[0]), "+f"(c[1]), "+f"(c[2]), "+f"(c[3])
        : "r"(a[0]), "r"(a[1]), "r"(a[2]), "r"(a[3]), "r"(b[0]), "r"(b[1]));
}
__device__ __forceinline__ void ldsm4(unsigned* r, unsigned addr) {
    asm volatile(
        "ldmatrix.sync.aligned.m8n8.x4.shared.b16 {%0,%1,%2,%3}, [%4];\n"
        : "=r"(r[0]), "=r"(r[1]), "=r"(r[2]), "=r"(r[3]) : "r"(addr));
}
__device__ __forceinline__ void ldsm4t(unsigned* r, unsigned addr) {
    asm volatile(
        "ldmatrix.sync.aligned.m8n8.x4.trans.shared.b16 {%0,%1,%2,%3}, [%4];\n"
        : "=r"(r[0]), "=r"(r[1]), "=r"(r[2]), "=r"(r[3]) : "r"(addr));
}
__device__ __forceinline__ void cp16(uint32_t dst, const void* src, int sz) {
    asm volatile("cp.async.cg.shared.global [%0], [%1], 16, %2;"
                 :: "r"(dst), "l"(src), "r"(sz));
}

// smem buffer layout (bytes within one stage)
#define BUF_BYTES 37888
#define A_H_OFF 0
#define A_L_OFF 10240
#define B_H_OFF 20480
#define B_L_OFF 29184
#define LDA_B 80      // A row stride bytes (40 bf16)
#define LDB_B 272     // B row stride bytes (136 bf16)
#define SMEM_GEMM (2 * BUF_BYTES)

// -------- split-precision tensor-core multi-GEMM (cp.async double-buffer) ---
__global__ __launch_bounds__(256, 2)
void gemm_mma(const bf16* __restrict__ Ahi, const bf16* __restrict__ Alo,
              const bf16* __restrict__ A2hi, const bf16* __restrict__ A2lo,
              int off0, int off1, int off2,
              const float* __restrict__ bias,
              float* __restrict__ Cf,
              __half* __restrict__ F0, __half* __restrict__ F1,
              __half* __restrict__ F2,
              bf16* __restrict__ Ohi, bf16* __restrict__ Olo,
              int Nr, int Ktot, int Mout, int relu) {
    extern __shared__ char smem[];
    int tid = threadIdx.x;
    int lane = tid & 31;
    int wid = tid >> 5;
    int warpM = wid & 3;
    int warpN = wid >> 2;
    int row0 = blockIdx.y * 128;

    int gi, chf;
    if (Mout == 256) { gi = blockIdx.x >> 1; chf = blockIdx.x & 1; }
    else             { gi = blockIdx.x;      chf = 0; }
    int boff = (gi == 0) ? off0 : ((gi == 1) ? off1 : off2);
    const bf16* Bh = g_w_hi + boff;
    const bf16* Bl = g_w_lo + boff;
    __half* Ff = (gi == 0) ? F0 : ((gi == 1) ? F1 : F2);
    int col0 = chf * 128;

    float acc[2][8][4];
#pragma unroll
    for (int i = 0; i < 2; i++)
#pragma unroll
        for (int j = 0; j < 8; j++)
#pragma unroll
            for (int t = 0; t < 4; t++) acc[i][j][t] = 0.0f;

    // ldmatrix lane mapping
    int a_row = warpM * 32 + (lane & 15);
    int a_col8 = (lane >> 4) << 3;
    int b_row = lane & 15;
    int b_col = warpN * 64 + ((lane >> 4) << 3);

    // fill mapping
    int a_m = tid >> 1;
    int a_kq = (tid & 1) * 16;              // element offset in k
    uint32_t a_sm = (uint32_t)(a_m * LDA_B + a_kq * 2);
    int b_kk = tid >> 3;
    int b_n0 = (tid & 7) * 16;
    uint32_t b_sm = (uint32_t)(b_kk * LDB_B + b_n0 * 2);
    int grow = row0 + a_m;
    int a_ok = (grow < Nr) ? 16 : 0;

    uint32_t sbase = (uint32_t)__cvta_generic_to_shared(smem);
    int T = Ktot >> 5;

#define ISSUE_TILE(t)                                                        \
    do {                                                                     \
        int k0_ = (t) * 32;                                                  \
        const bf16* ah_ = (k0_ < 256) ? Ahi : A2hi;                          \
        const bf16* al_ = (k0_ < 256) ? Alo : A2lo;                          \
        int kb_ = k0_ & 255;                                                 \
        uint32_t bb_ = sbase + ((t) & 1) * BUF_BYTES;                        \
        const char* gAh = (const char*)(ah_ + (size_t)grow * 256 + kb_ + a_kq); \
        const char* gAl = (const char*)(al_ + (size_t)grow * 256 + kb_ + a_kq); \
        cp16(bb_ + A_H_OFF + a_sm,      gAh,      a_ok);                     \
        cp16(bb_ + A_H_OFF + a_sm + 16, gAh + 16, a_ok);                     \
        cp16(bb_ + A_L_OFF + a_sm,      gAl,      a_ok);                     \
        cp16(bb_ + A_L_OFF + a_sm + 16, gAl + 16, a_ok);                     \
        const char* gBh = (const char*)(Bh + (size_t)(k0_ + b_kk) * Mout + col0 + b_n0); \
        const char* gBl = (const char*)(Bl + (size_t)(k0_ + b_kk) * Mout + col0 + b_n0); \
        cp16(bb_ + B_H_OFF + b_sm,      gBh,      16);                       \
        cp16(bb_ + B_H_OFF + b_sm + 16, gBh + 16, 16);                       \
        cp16(bb_ + B_L_OFF + b_sm,      gBl,      16);                       \
        cp16(bb_ + B_L_OFF + b_sm + 16, gBl + 16, 16);                       \
        asm volatile("cp.async.commit_group;");                              \
    } while (0)

    ISSUE_TILE(0);

    for (int t = 0; t < T; t++) {
        if (t + 1 < T) {
            ISSUE_TILE(t + 1);
            asm volatile("cp.async.wait_group 1;");
        } else {
            asm volatile("cp.async.wait_group 0;");
        }
        __syncthreads();

        uint32_t bb = sbase + (t & 1) * BUF_BYTES;
#pragma unroll
        for (int ks = 0; ks < 2; ks++) {
            unsigned ah[2][4], al[2][4], bh[4][4], bl[4][4];
#pragma unroll
            for (int u = 0; u < 2; u++) {
                uint32_t ao = bb + (uint32_t)((a_row + u * 16) * LDA_B +
                                              (ks * 16 + a_col8) * 2);
                ldsm4(ah[u], ao + A_H_OFF);
                ldsm4(al[u], ao + A_L_OFF);
            }
#pragma unroll
            for (int g = 0; g < 4; g++) {
                uint32_t bo = bb + (uint32_t)((ks * 16 + b_row) * LDB_B +
                                              (b_col + g * 16) * 2);
                ldsm4t(bh[g], bo + B_H_OFF);
                ldsm4t(bl[g], bo + B_L_OFF);
            }
#pragma unroll
            for (int i = 0; i < 2; i++) {
#pragma unroll
                for (int j = 0; j < 8; j++) {
                    mma_bf16(acc[i][j], ah[i], &bh[j >> 1][(j & 1) * 2]);
                    mma_bf16(acc[i][j], ah[i], &bl[j >> 1][(j & 1) * 2]);
                    mma_bf16(acc[i][j], al[i], &bh[j >> 1][(j & 1) * 2]);
                }
            }
        }
        __syncthreads();
    }
#undef ISSUE_TILE

    // ---- epilogue ----
#pragma unroll
    for (int i = 0; i < 2; i++) {
        int rbase = row0 + warpM * 32 + i * 16 + (lane >> 2);
#pragma unroll
        for (int j = 0; j < 8; j++) {
            int c = col0 + warpN * 64 + j * 8 + (lane & 3) * 2;
            float b0 = bias ? bias[c] : 0.0f;
            float b1 = bias ? bias[c + 1] : 0.0f;
            float v0 = acc[i][j][0] + b0;
            float v1 = acc[i][j][1] + b1;
            float v2 = acc[i][j][2] + b0;
            float v3 = acc[i][j][3] + b1;
            if (relu) {
                v0 = fmaxf(v0, 0.f); v1 = fmaxf(v1, 0.f);
                v2 = fmaxf(v2, 0.f); v3 = fmaxf(v3, 0.f);
            }
            if (Ff) {
                if (rbase < Nr)
                    *reinterpret_cast<__half2*>(&Ff[(size_t)rbase * Mout + c]) =
                        __floats2half2_rn(v0, v1);
                if (rbase + 8 < Nr)
                    *reinterpret_cast<__half2*>(
                        &Ff[(size_t)(rbase + 8) * Mout + c]) =
                        __floats2half2_rn(v2, v3);
            } else if (Ohi) {
                bf16 h0, l0, h1, l1;
                if (rbase < Nr) {
                    split_bf16(v0, h0, l0);
                    split_bf16(v1, h1, l1);
                    __nv_bfloat162 ph, pl;
                    ph.x = h0; ph.y = h1; pl.x = l0; pl.y = l1;
                    *reinterpret_cast<__nv_bfloat162*>(
                        &Ohi[(size_t)rbase * Mout + c]) = ph;
                    *reinterpret_cast<__nv_bfloat162*>(
                        &Olo[(size_t)rbase * Mout + c]) = pl;
                }
                if (rbase + 8 < Nr) {
                    split_bf16(v2, h0, l0);
                    split_bf16(v3, h1, l1);
                    __nv_bfloat162 ph, pl;
                    ph.x = h0; ph.y = h1; pl.x = l0; pl.y = l1;
                    *reinterpret_cast<__nv_bfloat162*>(
                        &Ohi[(size_t)(rbase + 8) * Mout + c]) = ph;
                    *reinterpret_cast<__nv_bfloat162*>(
                        &Olo[(size_t)(rbase + 8) * Mout + c]) = pl;
                }
            } else {
                if (rbase < Nr)
                    *reinterpret_cast<float2*>(&Cf[(size_t)rbase * Mout + c]) =
                        make_float2(v0, v1);
                if (rbase + 8 < Nr)
                    *reinterpret_cast<float2*>(
                        &Cf[(size_t)(rbase + 8) * Mout + c]) =
                        make_float2(v2, v3);
            }
        }
    }
}

// ---------------- edge attention: attn = leaky(scale*<Q[d],K[s]> + eb) ------
__global__ void attn_kernel(const float* __restrict__ edge_attr,
                            const float* __restrict__ We_l) {
    int idx = blockIdx.x * blockDim.x + threadIdx.x;
    float a = -3.4e38f;
    if (idx < N_EDGES * NHEAD) {
        int e = idx >> 3;
        int nh = idx & 7;
        int s = g_src[e];
        int d = g_dst[e];
        const uint4* q4 =
            reinterpret_cast<const uint4*>(g_qh + d * HID + nh * HDIM);
        const uint4* k4 =
            reinterpret_cast<const uint4*>(g_kh + s * HID + nh * HDIM);
        float acc = 0.0f;
#pragma unroll
        for (int i = 0; i < 4; i++) {
            uint4 qa = q4[i];
            uint4 ka = k4[i];
            const __half2* qh = reinterpret_cast<const __half2*>(&qa);
            const __half2* kh = reinterpret_cast<const __half2*>(&ka);
#pragma unroll
            for (int j = 0; j < 4; j++) {
                float2 qf = __half22float2(qh[j]);
                float2 kf = __half22float2(kh[j]);
                acc = fmaf(qf.x, kf.x, acc);
                acc = fmaf(qf.y, kf.y, acc);
            }
        }
        float eb = edge_attr[e * 3 + 0] * We_l[nh] +
                   edge_attr[e * 3 + 1] * We_l[8 + nh] +
                   edge_attr[e * 3 + 2] * We_l[16 + nh];
        a = acc * ATTN_SCALE + eb;
        a = (a > 0.0f) ? a : 0.2f * a;       // leaky_relu
        g_attn[idx] = a;
    }
    __shared__ float smax[8];
    float w = a;
#pragma unroll
    for (int o = 16; o > 0; o >>= 1)
        w = fmaxf(w, __shfl_down_sync(0xffffffffu, w, o));
    int warp = threadIdx.x >> 5, lane = threadIdx.x & 31;
    if (lane == 0) smax[warp] = w;
    __syncthreads();
    if (warp == 0) {
        w = (lane < 8) ? smax[lane] : -3.4e38f;
#pragma unroll
        for (int o = 4; o > 0; o >>= 1)
            w = fmaxf(w, __shfl_down_sync(0xffffffffu, w, o));
        if (lane == 0) atomicMax(&g_maxu, f2o(w));
    }
}

// ---------------- per-node softmax: exp + sum, single pass ------------------
// writes exp(a-m) into g_attn and 1/sum into g_inv.
__global__ void node_softmax() {
    int warp = threadIdx.x >> 5;
    int lane = threadIdx.x & 31;
    int n = blockIdx.x * 8 + warp;
    if (n >= N_NODES) return;
    int row = g_rowstart[n];
    int deg = g_rowstart[n + 1] - row;
    float m = o2f(g_maxu);
#pragma unroll
    for (int h = 0; h < NHEAD; h++) {
        float sum = 0.0f;
        for (int j = lane; j < deg; j += 32) {
            int e = g_perm[row + j];
            float v = __expf(g_attn[e * NHEAD + h] - m);
            g_attn[e * NHEAD + h] = v;
            sum += v;
        }
#pragma unroll
        for (int o = 16; o > 0; o >>= 1)
            sum += __shfl_xor_sync(0xffffffffu, sum, o);
        if (lane == 0)
            g_inv[n * NHEAD + h] = 1.0f / fmaxf(sum, 1e-12f);
    }
}

// ---------------- weighted V aggregation (CSR gather, fp16 V) ---------------
__global__ void agg_gather() {
    __shared__ int s_e[256];
    __shared__ int s_s[256];
    int n = blockIdx.x;
    int c = threadIdx.x;
    int nh = c >> 5;
    int row = g_rowstart[n];
    int deg = g_rowstart[n + 1] - row;
    float inv = g_inv[n * NHEAD + nh];
    float acc = 0.0f;
    for (int chunk = 0; chunk < deg; chunk += 256) {
        int j = chunk + c;
        if (j < deg) {
            int e = g_perm[row + j];
            s_e[c] = e;
            s_s[c] = g_src[e];
        }
        __syncthreads();
        int cnt = min(256, deg - chunk);
        for (int jj = 0; jj < cnt; jj++) {
            int e = s_e[jj];
            int s = s_s[jj];
            acc += g_attn[e * NHEAD + nh] * __half2float(g_vh[s * HID + c]);
        }
        __syncthreads();
    }
    acc *= inv;
    bf16 hi, lo;
    split_bf16(acc, hi, lo);
    g_agg_hi[n * HID + c] = hi;
    g_agg_lo[n * HID + c] = lo;
}

// ---------------- residual + LayerNorm: h = LN(h + upd)*gamma + beta --------
__global__ void ln_kernel(const float* __restrict__ upd,
                          const float* __restrict__ gamma_l,
                          const float* __restrict__ beta_l) {
    int n = blockIdx.x;
    int t = threadIdx.x;   // 256
    float x = g_h[n * HID + t] + upd[n * HID + t];
    __shared__ float s1[8], s2[8];
    float a = x, b = x * x;
#pragma unroll
    for (int o = 16; o > 0; o >>= 1) {
        a += __shfl_down_sync(0xffffffffu, a, o);
        b += __shfl_down_sync(0xffffffffu, b, o);
    }
    int warp = t >> 5, lane = t & 31;
    if (lane == 0) { s1[warp] = a; s2[warp] = b; }
    __syncthreads();
    if (warp == 0) {
        a = (lane < 8) ? s1[lane] : 0.0f;
        b = (lane < 8) ? s2[lane] : 0.0f;
#pragma unroll
        for (int o = 4; o > 0; o >>= 1) {
            a += __shfl_down_sync(0xffffffffu, a, o);
            b += __shfl_down_sync(0xffffffffu, b, o);
        }
        if (lane == 0) { s1[0] = a; s2[0] = b; }
    }
    __syncthreads();
    float mu = s1[0] * (1.0f / HID);
    float var = s2[0] * (1.0f / HID) - mu * mu;
    float r = (x - mu) * rsqrtf(var + 1e-5f) * gamma_l[t] + beta_l[t];
    g_h[n * HID + t] = r;
    bf16 hi, lo;
    split_bf16(r, hi, lo);
    g_h_hi[n * HID + t] = hi;
    g_h_lo[n * HID + t] = lo;
}

// ---------------- output head 2: out = hidden(N,128) @ W2(128,1) + b2 -------
__global__ void head2_kernel(const float* __restrict__ hidden,
                             const float* __restrict__ W2,
                             const float* __restrict__ b2,
                             float* __restrict__ out) {
    int gw = (blockIdx.x * blockDim.x + threadIdx.x) >> 5;
    int lane = threadIdx.x & 31;
    if (gw >= N_NODES) return;
    float acc = 0.0f;
#pragma unroll
    for (int i = 0; i < 4; i++) {
        int c = lane + i * 32;
        acc += hidden[gw * 128 + c] * W2[c];
    }
#pragma unroll
    for (int o = 16; o > 0; o >>= 1)
        acc += __shfl_down_sync(0xffffffffu, acc, o);
    if (lane == 0) out[gw] = acc + b2[0];
}

// ---------------- launch ----------------------------------------------------
extern "C" void kernel_launch(void* const* d_in, const int* in_sizes, int n_in,
                              void* d_out, int out_size) {
    const float* x         = (const float*)d_in[0];
    const float* edge_attr = (const float*)d_in[1];
    const float* W_in      = (const float*)d_in[2];
    const float* b_in      = (const float*)d_in[3];
    const float* Wq        = (const float*)d_in[4];
    const float* Wk        = (const float*)d_in[5];
    const float* Wv        = (const float*)d_in[6];
    const float* We        = (const float*)d_in[7];
    const float* Wo        = (const float*)d_in[8];
    const float* bo        = (const float*)d_in[9];
    const float* Wm        = (const float*)d_in[10];
    const float* bm        = (const float*)d_in[11];
    const float* gamma     = (const float*)d_in[12];
    const float* beta      = (const float*)d_in[13];
    const float* Wh1       = (const float*)d_in[14];
    const float* bh1       = (const float*)d_in[15];
    const float* Wh2       = (const float*)d_in[16];
    const float* bh2       = (const float*)d_in[17];
    const int*   ei_raw    = (const int*)d_in[18];

    bf16 *phhi, *phlo, *pagghi, *pagglo, *paohi, *paolo;
    float *pupd, *phid;
    __half *pqh, *pkh, *pvh;
    cudaGetSymbolAddress((void**)&phhi,   g_h_hi);
    cudaGetSymbolAddress((void**)&phlo,   g_h_lo);
    cudaGetSymbolAddress((void**)&pagghi, g_agg_hi);
    cudaGetSymbolAddress((void**)&pagglo, g_agg_lo);
    cudaGetSymbolAddress((void**)&paohi,  g_ao_hi);
    cudaGetSymbolAddress((void**)&paolo,  g_ao_lo);
    cudaGetSymbolAddress((void**)&pupd,   g_upd);
    cudaGetSymbolAddress((void**)&phid,   g_hid);
    cudaGetSymbolAddress((void**)&pqh,    g_qh);
    cudaGetSymbolAddress((void**)&pkh,    g_kh);
    cudaGetSymbolAddress((void**)&pvh,    g_vh);

    cudaFuncSetAttribute(gemm_mma, cudaFuncAttributeMaxDynamicSharedMemorySize,
                         SMEM_GEMM);

    const int NH_ELEMS = N_NODES * HID;

    // decode edge indices + build CSR (by dst)
    detect_idx<<<1, 256>>>(ei_raw);
    convert_idx<<<(N_EDGES + 255) / 256, 256>>>(ei_raw);
    zero_cnt<<<(N_NODES + 255) / 256, 256>>>();
    count_deg<<<(N_EDGES + 255) / 256, 256>>>();
    scan_rowstart<<<1, 1024>>>();
    copy_cursor<<<(N_NODES + 255) / 256, 256>>>();
    scatter_perm<<<(N_EDGES + 255) / 256, 256>>>();

    // pre-convert weights to bf16 hi/lo
    convert_w<<<(196608 + 255) / 256, 256>>>(Wq, 196608, OFF_WQ);
    convert_w<<<(196608 + 255) / 256, 256>>>(Wk, 196608, OFF_WK);
    convert_w<<<(196608 + 255) / 256, 256>>>(Wv, 196608, OFF_WV);
    convert_w<<<(196608 + 255) / 256, 256>>>(Wo, 196608, OFF_WO);
    convert_w<<<(393216 + 255) / 256, 256>>>(Wm, 393216, OFF_WM);
    convert_w<<<(32768 + 255) / 256, 256>>>(Wh1, 32768, OFF_WH1);

    input_proj<<<(NH_ELEMS + 255) / 256, 256>>>(x, W_in, b_in);

    int rows = (N_NODES + 127) / 128;   // 391
    dim3 gridQKV(6, rows);
    dim3 grid1(2, rows);
    dim3 gridHead(1, rows);

    for (int l = 0; l < NLAYER; l++) {
        int offQ = OFF_WQ + l * 65536;
        int offK = OFF_WK + l * 65536;
        int offV = OFF_WV + l * 65536;
        int offO = OFF_WO + l * 65536;
        int offM = OFF_WM + l * 131072;
        const float* We_l = We + l * 3 * NHEAD;
        const float* bo_l = bo + l * HID;
        const float* bm_l = bm + l * HID;
        const float* ga_l = gamma + l * HID;
        const float* be_l = beta + l * HID;

        // fused QKV: all fp16 out
        gemm_mma<<<gridQKV, 256, SMEM_GEMM>>>(
            phhi, phlo, nullptr, nullptr, offQ, offK, offV, nullptr,
            nullptr, pqh, pkh, pvh, nullptr, nullptr, N_NODES, 256, 256, 0);

        zero_maxu<<<1, 1>>>();
        attn_kernel<<<(N_EDGES * NHEAD + 255) / 256, 256>>>(edge_attr, We_l);
        node_softmax<<<(N_NODES + 7) / 8, 256>>>();
        agg_gather<<<N_NODES, 256>>>();

        // aggO = agg @ Wo + bo  -> bf16 hilo
        gemm_mma<<<grid1, 256, SMEM_GEMM>>>(
            pagghi, pagglo, nullptr, nullptr, offO, offO, offO, bo_l,
            nullptr, nullptr, nullptr, nullptr, paohi, paolo,
            N_NODES, 256, 256, 0);
        // upd = relu(concat([h, aggO]) @ Wm + bm)  -> fp32
        gemm_mma<<<grid1, 256, SMEM_GEMM>>>(
            phhi, phlo, paohi, paolo, offM, offM, offM, bm_l,
            pupd, nullptr, nullptr, nullptr, nullptr, nullptr,
            N_NODES, 512, 256, 1);
        // h = LN(h + upd) * gamma + beta  (+ hilo refresh)
        ln_kernel<<<N_NODES, 256>>>(pupd, ga_l, be_l);
    }

    // head: hidden = relu(h @ Wh1 + bh1) -> fp32; out = hidden @ Wh2 + bh2
    gemm_mma<<<gridHead, 256, SMEM_GEMM>>>(
        phhi, phlo, nullptr, nullptr, OFF_WH1, OFF_WH1, OFF_WH1, bh1,
        phid, nullptr, nullptr, nullptr, nullptr, nullptr,
        N_NODES, 256, 128, 1);
    head2_kernel<<<(N_NODES * 32 + 255) / 256, 256>>>(phid, Wh2, bh2,
                                                      (float*)d_out);
}